// round 9
// baseline (speedup 1.0000x reference)
#include <cuda_runtime.h>
#include <cuda_fp16.h>
#include <cstdint>

// Problem constants: B=8192, O=64, D=64, K=64
#define BB   8192
#define OO   64
#define DD   64
#define JJN  65                 // 0 = left-linear, 1..63 cubic, 64 = right-linear
#define SLICE (JJN * 32)        // uint4 entries per d-slice = 2080 (fp16-packed, o-pairs)
#define SLICE_BYTES (SLICE * 16) // 33280
#define NDC  4                  // d-chunks (split-K)
#define DCH  (DD / NDC)         // 16
#define BT   256                // b-tile per CTA
#define NBT  (BB / BT)          // 32
#define NSTAGE 4                // DMA pipeline depth

typedef unsigned long long u64;

// Static device scratch
__device__ uint4 g_Ph[DD * SLICE];        // packed cubic coeffs, 2.13 MB
__device__ float g_part[NDC * BB * OO];   // split-K partials, 8 MB

// ---------------------------------------------------------------- asm helpers
__device__ __forceinline__ u64 pk2(float a, float b) {
    u64 r; asm("mov.b64 %0, {%1, %2};" : "=l"(r) : "f"(a), "f"(b)); return r;
}
__device__ __forceinline__ float2 upk2(u64 a) {
    float2 r; asm("mov.b64 {%0, %1}, %2;" : "=f"(r.x), "=f"(r.y) : "l"(a)); return r;
}
__device__ __forceinline__ u64 add2(u64 a, u64 b) {
    u64 d; asm("add.rn.f32x2 %0, %1, %2;" : "=l"(d) : "l"(a), "l"(b)); return d;
}
__device__ __forceinline__ void mbar_init(uint32_t mbar, uint32_t cnt) {
    asm volatile("mbarrier.init.shared.b64 [%0], %1;" :: "r"(mbar), "r"(cnt) : "memory");
}
__device__ __forceinline__ void mbar_expect_tx(uint32_t mbar, uint32_t bytes) {
    asm volatile("mbarrier.arrive.expect_tx.shared::cta.b64 _, [%0], %1;"
                 :: "r"(mbar), "r"(bytes) : "memory");
}
__device__ __forceinline__ void mbar_arrive(uint32_t mbar) {
    asm volatile("mbarrier.arrive.release.cta.shared::cta.b64 _, [%0];"
                 :: "r"(mbar) : "memory");
}
__device__ __forceinline__ void bulk_g2s(uint32_t dst, const void* src, uint32_t bytes,
                                         uint32_t mbar) {
    asm volatile("cp.async.bulk.shared::cta.global.mbarrier::complete_tx::bytes "
                 "[%0], [%1], %2, [%3];"
                 :: "r"(dst), "l"(src), "r"(bytes), "r"(mbar) : "memory");
}
__device__ __forceinline__ void mbar_wait(uint32_t mbar, uint32_t parity) {
    asm volatile(
        "{\n"
        ".reg .pred P;\n"
        "W%=:\n"
        "mbarrier.try_wait.parity.acquire.cta.shared::cta.b64 P, [%0], %1, 0x989680;\n"
        "@P bra D%=;\n"
        "bra W%=;\n"
        "D%=:\n"
        "}"
        :: "r"(mbar), "r"(parity) : "memory");
}

// ---------------------------------------------------------------- PCHIP (exact reference math)
__device__ __forceinline__ float pchip_end(float d0, float d1) {
    float s = 0.5f * (3.0f * d0 - d1);
    if (s * d0 <= 0.0f) s = 0.0f;
    else if (d0 * d1 < 0.0f && fabsf(s) > 3.0f * fabsf(d0)) s = 3.0f * d0;
    return s;
}
__device__ __forceinline__ float pchip_mid(float dp, float dn) {
    return (dp * dn > 0.0f) ? (2.0f * dp * dn / (dp + dn + 1e-12f)) : 0.0f;
}
__device__ __forceinline__ float4 pchip_emit(int jj, float ya, float yb, float yc, float yd) {
    const float inv_h = 15.75f;     // 63/4 exact
    const float h = 4.0f / 63.0f;
    float dab = (yb - ya) * inv_h;
    float dbc = (yc - yb) * inv_h;
    float dcd = (yd - yc) * inv_h;
    float4 p;
    if (jj == 0) {
        p = make_float4(ya, h * pchip_end(dab, dbc), 0.0f, 0.0f);
    } else if (jj == 64) {
        p = make_float4(yd, h * pchip_end(dcd, dbc), 0.0f, 0.0f);
    } else {
        float y0v, y1v, m0v, m1v;
        if (jj == 1)       { y0v = ya; y1v = yb; m0v = pchip_end(dab, dbc); m1v = pchip_mid(dab, dbc); }
        else if (jj == 63) { y0v = yc; y1v = yd; m0v = pchip_mid(dbc, dcd); m1v = pchip_end(dcd, dbc); }
        else               { y0v = yb; y1v = yc; m0v = pchip_mid(dab, dbc); m1v = pchip_mid(dbc, dcd); }
        float M0 = h * m0v, M1 = h * m1v;
        p.x = y0v;
        p.y = M0;
        p.z = -3.0f * y0v + 3.0f * y1v - 2.0f * M0 - M1;
        p.w =  2.0f * y0v - 2.0f * y1v + M0 + M1;
    }
    return p;
}

// ---------------------------------------------------------------- prep (R7 version, unchanged)
// grid (DD, 9), 256 threads. CTA (d, blk) covers jj in [blk*8, blk*8+7] (clip at 64).
__global__ __launch_bounds__(256) void kan_prep(const float* __restrict__ coeffs) {
    __shared__ float sy[OO * 13];   // [o][kk] window, pad 13

    const int d   = blockIdx.x;
    const int blk = blockIdx.y;
    const int lo  = blk * 8;
    const int wlo = min(max(lo - 2, 0), 52);   // 12-knot window [wlo, wlo+11]

    for (int e = threadIdx.x; e < OO * 12; e += 256) {
        int o = e / 12, kk = e - o * 12;
        sy[o * 13 + kk] = coeffs[(o << 12) + (d << 6) + wlo + kk];
    }
    __syncthreads();

    const int wi = threadIdx.x >> 5, lane = threadIdx.x & 31;
    const int jj = lo + wi;
    if (jj > 64) return;

    int s = (jj == 0) ? 0 : ((jj == 64) ? 60 : min(max(jj - 2, 0), 60));
    int base = s - wlo;                         // in [0, 8]

    const float* r0 = &sy[lane * 13 + base];
    const float* r1 = &sy[(lane + 32) * 13 + base];
    float4 pa = pchip_emit(jj, r0[0], r0[1], r0[2], r0[3]);
    float4 pb = pchip_emit(jj, r1[0], r1[1], r1[2], r1[3]);

    __half2 h0 = __floats2half2_rn(pa.x, pb.x);
    __half2 h1 = __floats2half2_rn(pa.y, pb.y);
    __half2 h2 = __floats2half2_rn(pa.z, pb.z);
    __half2 h3 = __floats2half2_rn(pa.w, pb.w);
    uint4 q;
    q.x = *reinterpret_cast<uint32_t*>(&h0);
    q.y = *reinterpret_cast<uint32_t*>(&h1);
    q.z = *reinterpret_cast<uint32_t*>(&h2);
    q.w = *reinterpret_cast<uint32_t*>(&h3);
    g_Ph[d * SLICE + (jj << 5) + lane] = q;
}

// ---------------------------------------------------------------- main contraction
// grid (NBT, NDC) = (32, 4) = 128 CTAs, 512 threads = 16 warps.
// 4-deep cp.async.bulk pipeline; per-buffer full (tx) + empty (16-warp) mbarriers.
// No __syncthreads in the dd loop — warps run asynchronously, skew bounded by depth.
__global__ __launch_bounds__(512, 1) void kan_main(const float* __restrict__ x,
                                                   float* __restrict__ part) {
    extern __shared__ char smraw[];
    uint4* sP = reinterpret_cast<uint4*>(smraw);                          // NSTAGE * SLICE uint4
    float* sx = reinterpret_cast<float*>(smraw + NSTAGE * SLICE_BYTES);   // DCH * BT floats
    char* mraw = smraw + NSTAGE * SLICE_BYTES + DCH * BT * 4;
    uint32_t fullB  = (uint32_t)__cvta_generic_to_shared(mraw);           // 4 x 8B
    uint32_t emptyB = fullB + NSTAGE * 8;                                 // 4 x 8B
    uint32_t sb = (uint32_t)__cvta_generic_to_shared(sP);

    const int bt = blockIdx.x, dc = blockIdx.y;
    const int tid = threadIdx.x;
    const int w = tid >> 5, lane = tid & 31;
    const int dbase = dc * DCH;
    const int b0g = bt * BT;

    // load x tile [BT][DCH] -> sx[dd][b_local]
    for (int e = tid; e < BT * 4; e += 512) {
        int bl = e >> 2, seg = e & 3;
        float4 v = *reinterpret_cast<const float4*>(x + (size_t)(b0g + bl) * DD + dbase + seg * 4);
        sx[(seg * 4 + 0) * BT + bl] = v.x;
        sx[(seg * 4 + 1) * BT + bl] = v.y;
        sx[(seg * 4 + 2) * BT + bl] = v.z;
        sx[(seg * 4 + 3) * BT + bl] = v.w;
    }

    if (tid == 0) {
        #pragma unroll
        for (int s = 0; s < NSTAGE; s++) {
            mbar_init(fullB  + s * 8, 1);    // tx-based
            mbar_init(emptyB + s * 8, 16);   // one arrive per warp
        }
    }
    __syncthreads();   // mbar init + sx visible

    // prime the pipeline: 4 slices in flight
    if (tid == 0) {
        #pragma unroll
        for (int s = 0; s < NSTAGE; s++) {
            mbar_expect_tx(fullB + s * 8, SLICE_BYTES);
            bulk_g2s(sb + (uint32_t)s * SLICE_BYTES,
                     g_Ph + (size_t)(dbase + s) * SLICE, SLICE_BYTES, fullB + s * 8);
        }
    }

    u64 acc[16];
    #pragma unroll
    for (int i = 0; i < 16; i++) acc[i] = 0ULL;   // bit pattern of (0.f, 0.f)

    for (int dd = 0; dd < DCH; dd++) {
        const int s  = dd & (NSTAGE - 1);
        const uint32_t ph = (dd >> 2) & 1;
        mbar_wait(fullB + s * 8, ph);
        const uint4* cur = sP + s * SLICE + lane;

        // per-lane (jj, u) for this warp's 16 b's (lanes 16-31 mirror 0-15),
        // packed as (off << 16) | fp16(u)
        float xv = sx[dd * BT + (w << 4) + (lane & 15)];
        float t = (xv + 2.0f) * 15.75f;
        float f = fminf(fmaxf(floorf(t), 0.0f), 62.0f);
        int jj; float u;
        if (t < 0.0f)       { jj = 0;  u = t; }
        else if (t > 63.0f) { jj = 64; u = t - 63.0f; }
        else                { jj = (int)f + 1; u = t - f; }
        unsigned pk = ((unsigned)(jj << 5) << 16) |
                      (unsigned)__half_as_ushort(__float2half_rn(u));

        #pragma unroll
        for (int i = 0; i < 16; i++) {
            unsigned p   = __shfl_sync(0xffffffffu, pk, i);
            unsigned off = p >> 16;
            unsigned u2b = __byte_perm(p, p, 0x1010);     // half2(u, u)
            uint4 q = cur[off];
            __half2 uu = *reinterpret_cast<__half2*>(&u2b);
            __half2 hc0 = *reinterpret_cast<__half2*>(&q.x);
            __half2 hc1 = *reinterpret_cast<__half2*>(&q.y);
            __half2 hc2 = *reinterpret_cast<__half2*>(&q.z);
            __half2 hc3 = *reinterpret_cast<__half2*>(&q.w);
            __half2 r = __hfma2(hc3, uu, hc2);
            r = __hfma2(r, uu, hc1);
            r = __hfma2(r, uu, hc0);
            float2 rf = __half22float2(r);
            acc[i] = add2(acc[i], pk2(rf.x, rf.y));
        }

        // this warp is done reading buffer s
        if (lane == 0) mbar_arrive(emptyB + s * 8);

        // producer: refill slot s for dd+4 once all 16 warps have released it
        if (tid == 0 && dd + NSTAGE < DCH) {
            mbar_wait(emptyB + s * 8, ph);
            mbar_expect_tx(fullB + s * 8, SLICE_BYTES);
            bulk_g2s(sb + (uint32_t)s * SLICE_BYTES,
                     g_Ph + (size_t)(dbase + dd + NSTAGE) * SLICE, SLICE_BYTES, fullB + s * 8);
        }
    }

    // partials: part[dc][b][o]
    float* pdst = part + ((size_t)dc * BB + b0g + (w << 4)) * OO;
    #pragma unroll
    for (int i = 0; i < 16; i++) {
        float2 v = upk2(acc[i]);
        pdst[i * OO + lane]      = v.x;
        pdst[i * OO + 32 + lane] = v.y;
    }
}

// ---------------------------------------------------------------- split-K reduce + bias (float4)
__global__ void kan_reduce(const float* __restrict__ part, const float* __restrict__ bias,
                           float* __restrict__ out) {
    int idx = blockIdx.x * 256 + threadIdx.x;     // over B*O/4
    const float4* p4 = reinterpret_cast<const float4*>(part);
    float4 s = reinterpret_cast<const float4*>(bias)[idx & 15];
    #pragma unroll
    for (int c = 0; c < NDC; c++) {
        float4 v = p4[(size_t)c * (BB * OO / 4) + idx];
        s.x += v.x; s.y += v.y; s.z += v.z; s.w += v.w;
    }
    reinterpret_cast<float4*>(out)[idx] = s;
}

// ---------------------------------------------------------------- launch
extern "C" void kernel_launch(void* const* d_in, const int* in_sizes, int n_in,
                              void* d_out, int out_size) {
    const float* x      = (const float*)d_in[0];   // [8192, 64]
    const float* coeffs = (const float*)d_in[1];   // [64, 64, 64]
    const float* bias   = (const float*)d_in[2];   // [64]
    float* out = (float*)d_out;                    // [8192, 64]

    float* prt; cudaGetSymbolAddress((void**)&prt, g_part);

    const int smem_main = NSTAGE * SLICE_BYTES + DCH * BT * 4 + NSTAGE * 16;  // 149568
    cudaFuncSetAttribute(kan_main, cudaFuncAttributeMaxDynamicSharedMemorySize, smem_main);

    kan_prep<<<dim3(DD, 9), 256>>>(coeffs);
    kan_main<<<dim3(NBT, NDC), 512, smem_main>>>(x, prt);
    kan_reduce<<<(BB * OO / 4) / 256, 256>>>(prt, bias, out);
}

// round 10
// speedup vs baseline: 1.5193x; 1.5193x over previous
#include <cuda_runtime.h>
#include <cuda_fp16.h>
#include <cstdint>

// Problem constants: B=8192, O=64, D=64, K=64
#define BB   8192
#define OO   64
#define DD   64
#define JJN  65                 // 0 = left-linear, 1..63 cubic, 64 = right-linear
#define SLICE (JJN * 32)        // uint4 entries per d-slice = 2080 (fp16-packed, o-pairs)
#define SLICE_BYTES (SLICE * 16) // 33280
#define NDC  4                  // d-chunks (split-K)
#define DCH  (DD / NDC)         // 16
#define BT   256                // b-tile per CTA
#define NBT  (BB / BT)          // 32
#define NSTAGE 3                // staging depth (sync-based recycling)

typedef unsigned long long u64;

// Static device scratch
__device__ uint4 g_Ph[DD * SLICE];        // packed cubic coeffs, 2.13 MB
__device__ float g_part[NDC * BB * OO];   // split-K partials, 8 MB

// ---------------------------------------------------------------- asm helpers
__device__ __forceinline__ u64 pk2(float a, float b) {
    u64 r; asm("mov.b64 %0, {%1, %2};" : "=l"(r) : "f"(a), "f"(b)); return r;
}
__device__ __forceinline__ float2 upk2(u64 a) {
    float2 r; asm("mov.b64 {%0, %1}, %2;" : "=f"(r.x), "=f"(r.y) : "l"(a)); return r;
}
__device__ __forceinline__ u64 add2(u64 a, u64 b) {
    u64 d; asm("add.rn.f32x2 %0, %1, %2;" : "=l"(d) : "l"(a), "l"(b)); return d;
}
__device__ __forceinline__ void mbar_init(uint32_t mbar, uint32_t cnt) {
    asm volatile("mbarrier.init.shared.b64 [%0], %1;" :: "r"(mbar), "r"(cnt) : "memory");
}
__device__ __forceinline__ void mbar_expect_tx(uint32_t mbar, uint32_t bytes) {
    asm volatile("mbarrier.arrive.expect_tx.shared::cta.b64 _, [%0], %1;"
                 :: "r"(mbar), "r"(bytes) : "memory");
}
__device__ __forceinline__ void bulk_g2s(uint32_t dst, const void* src, uint32_t bytes,
                                         uint32_t mbar) {
    asm volatile("cp.async.bulk.shared::cta.global.mbarrier::complete_tx::bytes "
                 "[%0], [%1], %2, [%3];"
                 :: "r"(dst), "l"(src), "r"(bytes), "r"(mbar) : "memory");
}
__device__ __forceinline__ void mbar_wait(uint32_t mbar, uint32_t parity) {
    asm volatile(
        "{\n"
        ".reg .pred P;\n"
        "W%=:\n"
        "mbarrier.try_wait.parity.acquire.cta.shared::cta.b64 P, [%0], %1, 0x989680;\n"
        "@P bra D%=;\n"
        "bra W%=;\n"
        "D%=:\n"
        "}"
        :: "r"(mbar), "r"(parity) : "memory");
}

// ---------------------------------------------------------------- PCHIP (exact reference math)
__device__ __forceinline__ float pchip_end(float d0, float d1) {
    float s = 0.5f * (3.0f * d0 - d1);
    if (s * d0 <= 0.0f) s = 0.0f;
    else if (d0 * d1 < 0.0f && fabsf(s) > 3.0f * fabsf(d0)) s = 3.0f * d0;
    return s;
}
__device__ __forceinline__ float pchip_mid(float dp, float dn) {
    return (dp * dn > 0.0f) ? (2.0f * dp * dn / (dp + dn + 1e-12f)) : 0.0f;
}
__device__ __forceinline__ float4 pchip_emit(int jj, float ya, float yb, float yc, float yd) {
    const float inv_h = 15.75f;     // 63/4 exact
    const float h = 4.0f / 63.0f;
    float dab = (yb - ya) * inv_h;
    float dbc = (yc - yb) * inv_h;
    float dcd = (yd - yc) * inv_h;
    float4 p;
    if (jj == 0) {
        p = make_float4(ya, h * pchip_end(dab, dbc), 0.0f, 0.0f);
    } else if (jj == 64) {
        p = make_float4(yd, h * pchip_end(dcd, dbc), 0.0f, 0.0f);
    } else {
        float y0v, y1v, m0v, m1v;
        if (jj == 1)       { y0v = ya; y1v = yb; m0v = pchip_end(dab, dbc); m1v = pchip_mid(dab, dbc); }
        else if (jj == 63) { y0v = yc; y1v = yd; m0v = pchip_mid(dbc, dcd); m1v = pchip_end(dcd, dbc); }
        else               { y0v = yb; y1v = yc; m0v = pchip_mid(dab, dbc); m1v = pchip_mid(dbc, dcd); }
        float M0 = h * m0v, M1 = h * m1v;
        p.x = y0v;
        p.y = M0;
        p.z = -3.0f * y0v + 3.0f * y1v - 2.0f * M0 - M1;
        p.w =  2.0f * y0v - 2.0f * y1v + M0 + M1;
    }
    return p;
}

// ---------------------------------------------------------------- prep
// grid (DD, 9), 256 threads. CTA (d, blk) covers jj in [blk*8, blk*8+7] (clip at 64).
// Aligned 16-knot window loaded via float4 (one per thread), sy stride 17.
__global__ __launch_bounds__(256) void kan_prep(const float* __restrict__ coeffs) {
    __shared__ float sy[OO * 17];   // [o][kk], 16-knot window + pad

    const int d   = blockIdx.x;
    const int blk = blockIdx.y;
    const int lo  = blk * 8;
    const int wa  = min(max((lo - 2) & ~3, 0), 48);   // aligned window [wa, wa+15]

    // one float4 per thread: 64 o-rows x 4 quads
    {
        int o = threadIdx.x >> 2, qd = (threadIdx.x & 3) << 2;
        float4 v = *reinterpret_cast<const float4*>(coeffs + (o << 12) + (d << 6) + wa + qd);
        float* r = sy + o * 17 + qd;
        r[0] = v.x; r[1] = v.y; r[2] = v.z; r[3] = v.w;
    }
    __syncthreads();

    const int wi = threadIdx.x >> 5, lane = threadIdx.x & 31;
    const int jj = lo + wi;
    if (jj > 64) return;

    int s = (jj == 0) ? 0 : ((jj == 64) ? 60 : min(max(jj - 2, 0), 60));
    int base = s - wa;                          // in [0, 12]

    const float* r0 = &sy[lane * 17 + base];
    const float* r1 = &sy[(lane + 32) * 17 + base];
    float4 pa = pchip_emit(jj, r0[0], r0[1], r0[2], r0[3]);
    float4 pb = pchip_emit(jj, r1[0], r1[1], r1[2], r1[3]);

    __half2 h0 = __floats2half2_rn(pa.x, pb.x);
    __half2 h1 = __floats2half2_rn(pa.y, pb.y);
    __half2 h2 = __floats2half2_rn(pa.z, pb.z);
    __half2 h3 = __floats2half2_rn(pa.w, pb.w);
    uint4 q;
    q.x = *reinterpret_cast<uint32_t*>(&h0);
    q.y = *reinterpret_cast<uint32_t*>(&h1);
    q.z = *reinterpret_cast<uint32_t*>(&h2);
    q.w = *reinterpret_cast<uint32_t*>(&h3);
    g_Ph[d * SLICE + (jj << 5) + lane] = q;
}

// ---------------------------------------------------------------- main contraction
// grid (NBT, NDC) = (32, 4) = 128 CTAs, 512 threads = 16 warps.
// Depth-3 bulk-DMA staging with __syncthreads-based slot recycling:
// the per-dd barrier proves slot dd%3 is drained, then tid 0 refills it for dd+3.
__global__ __launch_bounds__(512, 1) void kan_main(const float* __restrict__ x,
                                                   float* __restrict__ part) {
    extern __shared__ char smraw[];
    uint4* sP = reinterpret_cast<uint4*>(smraw);                          // NSTAGE * SLICE uint4
    float* sx = reinterpret_cast<float*>(smraw + NSTAGE * SLICE_BYTES);   // DCH * BT floats
    uint32_t mbarBase = (uint32_t)__cvta_generic_to_shared(
        smraw + NSTAGE * SLICE_BYTES + DCH * BT * 4);                     // NSTAGE x 8B
    uint32_t sb = (uint32_t)__cvta_generic_to_shared(sP);

    const int bt = blockIdx.x, dc = blockIdx.y;
    const int tid = threadIdx.x;
    const int w = tid >> 5, lane = tid & 31;
    const int dbase = dc * DCH;
    const int b0g = bt * BT;

    // load x tile [BT][DCH] -> sx[dd][b_local]
    for (int e = tid; e < BT * 4; e += 512) {
        int bl = e >> 2, seg = e & 3;
        float4 v = *reinterpret_cast<const float4*>(x + (size_t)(b0g + bl) * DD + dbase + seg * 4);
        sx[(seg * 4 + 0) * BT + bl] = v.x;
        sx[(seg * 4 + 1) * BT + bl] = v.y;
        sx[(seg * 4 + 2) * BT + bl] = v.z;
        sx[(seg * 4 + 3) * BT + bl] = v.w;
    }

    if (tid == 0) {
        #pragma unroll
        for (int s = 0; s < NSTAGE; s++) mbar_init(mbarBase + s * 8, 1);
    }
    __syncthreads();   // mbar init + sx visible

    auto issue = [&](int dd, int slot) {
        uint32_t mb = mbarBase + (uint32_t)slot * 8;
        mbar_expect_tx(mb, SLICE_BYTES);
        bulk_g2s(sb + (uint32_t)slot * SLICE_BYTES,
                 g_Ph + (size_t)(dbase + dd) * SLICE, SLICE_BYTES, mb);
    };
    if (tid == 0) { issue(0, 0); issue(1, 1); issue(2, 2); }

    u64 acc[16];
    #pragma unroll
    for (int i = 0; i < 16; i++) acc[i] = 0ULL;   // bit pattern of (0.f, 0.f)

    int slot = 0, fill = 0;          // fill counts completions per slot via dd/3
    for (int dd = 0; dd < DCH; dd++) {
        uint32_t ph = (uint32_t)(dd / NSTAGE) & 1;
        mbar_wait(mbarBase + slot * 8, ph);
        const uint4* cur = sP + slot * SLICE + lane;

        // per-lane (jj, u) for this warp's 16 b's (lanes 16-31 mirror 0-15),
        // packed as (off << 16) | fp16(u)
        float xv = sx[dd * BT + (w << 4) + (lane & 15)];
        float t = (xv + 2.0f) * 15.75f;
        float f = fminf(fmaxf(floorf(t), 0.0f), 62.0f);
        int jj; float u;
        if (t < 0.0f)       { jj = 0;  u = t; }
        else if (t > 63.0f) { jj = 64; u = t - 63.0f; }
        else                { jj = (int)f + 1; u = t - f; }
        unsigned pk = ((unsigned)(jj << 5) << 16) |
                      (unsigned)__half_as_ushort(__float2half_rn(u));

        #pragma unroll
        for (int i = 0; i < 16; i++) {
            unsigned p   = __shfl_sync(0xffffffffu, pk, i);
            unsigned off = p >> 16;
            unsigned u2b = __byte_perm(p, p, 0x1010);     // half2(u, u)
            uint4 q = cur[off];
            __half2 uu = *reinterpret_cast<__half2*>(&u2b);
            __half2 hc0 = *reinterpret_cast<__half2*>(&q.x);
            __half2 hc1 = *reinterpret_cast<__half2*>(&q.y);
            __half2 hc2 = *reinterpret_cast<__half2*>(&q.z);
            __half2 hc3 = *reinterpret_cast<__half2*>(&q.w);
            __half2 r = __hfma2(hc3, uu, hc2);
            r = __hfma2(r, uu, hc1);
            r = __hfma2(r, uu, hc0);
            float2 rf = __half22float2(r);
            acc[i] = add2(acc[i], pk2(rf.x, rf.y));
        }

        __syncthreads();   // slot drained by all warps
        if (dd + NSTAGE < DCH && tid == 0) issue(dd + NSTAGE, slot);
        slot = (slot == NSTAGE - 1) ? 0 : slot + 1;
        (void)fill;
    }

    // partials: part[dc][b][o]
    float* pdst = part + ((size_t)dc * BB + b0g + (w << 4)) * OO;
    #pragma unroll
    for (int i = 0; i < 16; i++) {
        float2 v = upk2(acc[i]);
        pdst[i * OO + lane]      = v.x;
        pdst[i * OO + 32 + lane] = v.y;
    }
}

// ---------------------------------------------------------------- split-K reduce + bias (float4)
__global__ void kan_reduce(const float* __restrict__ part, const float* __restrict__ bias,
                           float* __restrict__ out) {
    int idx = blockIdx.x * 256 + threadIdx.x;     // over B*O/4
    const float4* p4 = reinterpret_cast<const float4*>(part);
    float4 s = reinterpret_cast<const float4*>(bias)[idx & 15];
    #pragma unroll
    for (int c = 0; c < NDC; c++) {
        float4 v = p4[(size_t)c * (BB * OO / 4) + idx];
        s.x += v.x; s.y += v.y; s.z += v.z; s.w += v.w;
    }
    reinterpret_cast<float4*>(out)[idx] = s;
}

// ---------------------------------------------------------------- launch
extern "C" void kernel_launch(void* const* d_in, const int* in_sizes, int n_in,
                              void* d_out, int out_size) {
    const float* x      = (const float*)d_in[0];   // [8192, 64]
    const float* coeffs = (const float*)d_in[1];   // [64, 64, 64]
    const float* bias   = (const float*)d_in[2];   // [64]
    float* out = (float*)d_out;                    // [8192, 64]

    float* prt; cudaGetSymbolAddress((void**)&prt, g_part);

    const int smem_main = NSTAGE * SLICE_BYTES + DCH * BT * 4 + NSTAGE * 8;  // 116248
    cudaFuncSetAttribute(kan_main, cudaFuncAttributeMaxDynamicSharedMemorySize, smem_main);

    kan_prep<<<dim3(DD, 9), 256>>>(coeffs);
    kan_main<<<dim3(NBT, NDC), 512, smem_main>>>(x, prt);
    kan_reduce<<<(BB * OO / 4) / 256, 256>>>(prt, bias, out);
}

// round 11
// speedup vs baseline: 1.9696x; 1.2964x over previous
#include <cuda_runtime.h>
#include <cuda_fp16.h>
#include <cstdint>

// Problem constants: B=8192, O=64, D=64, K=64
#define BB   8192
#define OO   64
#define DD   64
#define JJN  65                 // 0 = left-linear, 1..63 cubic, 64 = right-linear
#define SLICE (JJN * 32)        // uint4 entries per d-slice = 2080 (fp16-packed, o-pairs)
#define SLICE_BYTES (SLICE * 16) // 33280
#define NDC  4                  // d-chunks (split-K)
#define DCH  (DD / NDC)         // 16
#define BT   256                // b-tile per CTA
#define NBT  (BB / BT)          // 32

typedef unsigned long long u64;

// Static device scratch
__device__ uint4 g_Ph[DD * SLICE];        // packed cubic coeffs, 2.13 MB
__device__ float g_part[NDC * BB * OO];   // split-K partials, 8 MB
__device__ unsigned g_sync_done[NBT];     // monotonic arrival counters (4 per launch)

// ---------------------------------------------------------------- asm helpers
__device__ __forceinline__ u64 pk2(float a, float b) {
    u64 r; asm("mov.b64 %0, {%1, %2};" : "=l"(r) : "f"(a), "f"(b)); return r;
}
__device__ __forceinline__ float2 upk2(u64 a) {
    float2 r; asm("mov.b64 {%0, %1}, %2;" : "=f"(r.x), "=f"(r.y) : "l"(a)); return r;
}
__device__ __forceinline__ u64 add2(u64 a, u64 b) {
    u64 d; asm("add.rn.f32x2 %0, %1, %2;" : "=l"(d) : "l"(a), "l"(b)); return d;
}
__device__ __forceinline__ void mbar_init(uint32_t mbar, uint32_t cnt) {
    asm volatile("mbarrier.init.shared.b64 [%0], %1;" :: "r"(mbar), "r"(cnt) : "memory");
}
__device__ __forceinline__ void mbar_expect_tx(uint32_t mbar, uint32_t bytes) {
    asm volatile("mbarrier.arrive.expect_tx.shared::cta.b64 _, [%0], %1;"
                 :: "r"(mbar), "r"(bytes) : "memory");
}
__device__ __forceinline__ void bulk_g2s(uint32_t dst, const void* src, uint32_t bytes,
                                         uint32_t mbar) {
    asm volatile("cp.async.bulk.shared::cta.global.mbarrier::complete_tx::bytes "
                 "[%0], [%1], %2, [%3];"
                 :: "r"(dst), "l"(src), "r"(bytes), "r"(mbar) : "memory");
}
__device__ __forceinline__ void mbar_wait(uint32_t mbar, uint32_t parity) {
    asm volatile(
        "{\n"
        ".reg .pred P;\n"
        "W%=:\n"
        "mbarrier.try_wait.parity.acquire.cta.shared::cta.b64 P, [%0], %1, 0x989680;\n"
        "@P bra D%=;\n"
        "bra W%=;\n"
        "D%=:\n"
        "}"
        :: "r"(mbar), "r"(parity) : "memory");
}

// ---------------------------------------------------------------- PCHIP (exact reference math)
__device__ __forceinline__ float pchip_end(float d0, float d1) {
    float s = 0.5f * (3.0f * d0 - d1);
    if (s * d0 <= 0.0f) s = 0.0f;
    else if (d0 * d1 < 0.0f && fabsf(s) > 3.0f * fabsf(d0)) s = 3.0f * d0;
    return s;
}
__device__ __forceinline__ float pchip_mid(float dp, float dn) {
    return (dp * dn > 0.0f) ? (2.0f * dp * dn / (dp + dn + 1e-12f)) : 0.0f;
}
__device__ __forceinline__ float4 pchip_emit(int jj, float ya, float yb, float yc, float yd) {
    const float inv_h = 15.75f;     // 63/4 exact
    const float h = 4.0f / 63.0f;
    float dab = (yb - ya) * inv_h;
    float dbc = (yc - yb) * inv_h;
    float dcd = (yd - yc) * inv_h;
    float4 p;
    if (jj == 0) {
        p = make_float4(ya, h * pchip_end(dab, dbc), 0.0f, 0.0f);
    } else if (jj == 64) {
        p = make_float4(yd, h * pchip_end(dcd, dbc), 0.0f, 0.0f);
    } else {
        float y0v, y1v, m0v, m1v;
        if (jj == 1)       { y0v = ya; y1v = yb; m0v = pchip_end(dab, dbc); m1v = pchip_mid(dab, dbc); }
        else if (jj == 63) { y0v = yc; y1v = yd; m0v = pchip_mid(dbc, dcd); m1v = pchip_end(dcd, dbc); }
        else               { y0v = yb; y1v = yc; m0v = pchip_mid(dab, dbc); m1v = pchip_mid(dbc, dcd); }
        float M0 = h * m0v, M1 = h * m1v;
        p.x = y0v;
        p.y = M0;
        p.z = -3.0f * y0v + 3.0f * y1v - 2.0f * M0 - M1;
        p.w =  2.0f * y0v - 2.0f * y1v + M0 + M1;
    }
    return p;
}

// ---------------------------------------------------------------- prep (R10 version, measured 5.6us)
// grid (DD, 9), 256 threads. CTA (d, blk) covers jj in [blk*8, blk*8+7] (clip at 64).
__global__ __launch_bounds__(256) void kan_prep(const float* __restrict__ coeffs) {
    __shared__ float sy[OO * 17];   // [o][kk], 16-knot window + pad

    const int d   = blockIdx.x;
    const int blk = blockIdx.y;
    const int lo  = blk * 8;
    const int wa  = min(max((lo - 2) & ~3, 0), 48);   // aligned window [wa, wa+15]

    {
        int o = threadIdx.x >> 2, qd = (threadIdx.x & 3) << 2;
        float4 v = *reinterpret_cast<const float4*>(coeffs + (o << 12) + (d << 6) + wa + qd);
        float* r = sy + o * 17 + qd;
        r[0] = v.x; r[1] = v.y; r[2] = v.z; r[3] = v.w;
    }
    __syncthreads();

    const int wi = threadIdx.x >> 5, lane = threadIdx.x & 31;
    const int jj = lo + wi;
    if (jj > 64) return;

    int s = (jj == 0) ? 0 : ((jj == 64) ? 60 : min(max(jj - 2, 0), 60));
    int base = s - wa;                          // in [0, 12]

    const float* r0 = &sy[lane * 17 + base];
    const float* r1 = &sy[(lane + 32) * 17 + base];
    float4 pa = pchip_emit(jj, r0[0], r0[1], r0[2], r0[3]);
    float4 pb = pchip_emit(jj, r1[0], r1[1], r1[2], r1[3]);

    __half2 h0 = __floats2half2_rn(pa.x, pb.x);
    __half2 h1 = __floats2half2_rn(pa.y, pb.y);
    __half2 h2 = __floats2half2_rn(pa.z, pb.z);
    __half2 h3 = __floats2half2_rn(pa.w, pb.w);
    uint4 q;
    q.x = *reinterpret_cast<uint32_t*>(&h0);
    q.y = *reinterpret_cast<uint32_t*>(&h1);
    q.z = *reinterpret_cast<uint32_t*>(&h2);
    q.w = *reinterpret_cast<uint32_t*>(&h3);
    g_Ph[d * SLICE + (jj << 5) + lane] = q;
}

// ---------------------------------------------------------------- main + fused reduce
// grid (NBT, NDC) = (32, 4) = 128 CTAs, 512 threads = 16 warps.
// Staging: EXACT R7 skeleton — depth-2 cp.async.bulk, ph0/ph1, per-dd __syncthreads.
// Tail: per-bt last-CTA-done reduces the 4 split-K chunks + bias -> out (L2-hot).
__global__ __launch_bounds__(512, 1) void kan_main(const float* __restrict__ x,
                                                   const float* __restrict__ bias,
                                                   float* __restrict__ out) {
    extern __shared__ char smraw[];
    uint4* sP = reinterpret_cast<uint4*>(smraw);                      // 2 * SLICE uint4
    float* sx = reinterpret_cast<float*>(smraw + 2 * SLICE_BYTES);    // DCH * BT floats
    uint32_t mbarBase = (uint32_t)__cvta_generic_to_shared(
        smraw + 2 * SLICE_BYTES + DCH * BT * 4);                      // 2 x 8B mbarriers
    uint32_t sb = (uint32_t)__cvta_generic_to_shared(sP);
    __shared__ int s_last;

    const int bt = blockIdx.x, dc = blockIdx.y;
    const int tid = threadIdx.x;
    const int w = tid >> 5, lane = tid & 31;
    const int dbase = dc * DCH;
    const int b0g = bt * BT;

    // load x tile [BT][DCH] -> sx[dd][b_local]
    for (int e = tid; e < BT * 4; e += 512) {
        int bl = e >> 2, seg = e & 3;
        float4 v = *reinterpret_cast<const float4*>(x + (size_t)(b0g + bl) * DD + dbase + seg * 4);
        sx[(seg * 4 + 0) * BT + bl] = v.x;
        sx[(seg * 4 + 1) * BT + bl] = v.y;
        sx[(seg * 4 + 2) * BT + bl] = v.z;
        sx[(seg * 4 + 3) * BT + bl] = v.w;
    }

    if (tid == 0) {
        mbar_init(mbarBase, 1);
        mbar_init(mbarBase + 8, 1);
    }
    __syncthreads();   // mbar init visible + sx done

    auto issue = [&](int dd, int which) {
        uint32_t mb = mbarBase + (uint32_t)which * 8;
        mbar_expect_tx(mb, SLICE_BYTES);
        bulk_g2s(sb + (uint32_t)which * SLICE_BYTES,
                 g_Ph + (size_t)(dbase + dd) * SLICE, SLICE_BYTES, mb);
    };
    if (tid == 0) { issue(0, 0); issue(1, 1); }

    u64 acc[16];
    #pragma unroll
    for (int i = 0; i < 16; i++) acc[i] = 0ULL;   // bit pattern of (0.f, 0.f)

    uint32_t ph0 = 0, ph1 = 0;

    for (int dd = 0; dd < DCH; dd++) {
        int which = dd & 1;
        if (which == 0) { mbar_wait(mbarBase, ph0);     ph0 ^= 1; }
        else            { mbar_wait(mbarBase + 8, ph1); ph1 ^= 1; }
        uint4* cur = sP + which * SLICE;

        // per-lane (jj, u) for this warp's 16 b's (lanes 16-31 mirror 0-15),
        // packed as (off << 16) | fp16(u)
        float xv = sx[dd * BT + (w << 4) + (lane & 15)];
        float t = (xv + 2.0f) * 15.75f;
        float f = fminf(fmaxf(floorf(t), 0.0f), 62.0f);
        int jj; float u;
        if (t < 0.0f)       { jj = 0;  u = t; }
        else if (t > 63.0f) { jj = 64; u = t - 63.0f; }
        else                { jj = (int)f + 1; u = t - f; }
        unsigned pk = ((unsigned)(jj << 5) << 16) |
                      (unsigned)__half_as_ushort(__float2half_rn(u));

        #pragma unroll
        for (int i = 0; i < 16; i++) {
            unsigned p   = __shfl_sync(0xffffffffu, pk, i);
            unsigned off = p >> 16;
            unsigned u2b = __byte_perm(p, p, 0x1010);     // half2(u, u)
            uint4 q = cur[off + lane];
            __half2 uu = *reinterpret_cast<__half2*>(&u2b);
            __half2 hc0 = *reinterpret_cast<__half2*>(&q.x);
            __half2 hc1 = *reinterpret_cast<__half2*>(&q.y);
            __half2 hc2 = *reinterpret_cast<__half2*>(&q.z);
            __half2 hc3 = *reinterpret_cast<__half2*>(&q.w);
            __half2 r = __hfma2(hc3, uu, hc2);
            r = __hfma2(r, uu, hc1);
            r = __hfma2(r, uu, hc0);
            float2 rf = __half22float2(r);
            acc[i] = add2(acc[i], pk2(rf.x, rf.y));
        }

        __syncthreads();   // all warps done reading buffer `which`
        if (dd + 2 < DCH && tid == 0) issue(dd + 2, which);
    }

    // partials: part[dc][b][o]
    {
        float* pdst = g_part + ((size_t)dc * BB + b0g + (w << 4)) * OO;
        #pragma unroll
        for (int i = 0; i < 16; i++) {
            float2 v = upk2(acc[i]);
            pdst[i * OO + lane]      = v.x;
            pdst[i * OO + 32 + lane] = v.y;
        }
    }
    __threadfence();      // release partials
    __syncthreads();

    // tail: last CTA of this bt reduces the 4 chunks + bias (L2-hot)
    if (tid == 0) {
        unsigned o2 = atomicAdd(&g_sync_done[bt], 1u);
        s_last = ((o2 & 3u) == 3u) ? 1 : 0;
    }
    __syncthreads();
    if (s_last) {
        __threadfence();   // acquire siblings' partials
        const float4* p4 = reinterpret_cast<const float4*>(g_part);
        const float4* b4 = reinterpret_cast<const float4*>(bias);
        float4* o4p = reinterpret_cast<float4*>(out);
        for (int e = tid; e < BT * 16; e += 512) {     // BT*64/4 float4
            int bl = e >> 4, o4 = e & 15;
            float4 s = b4[o4];
            #pragma unroll
            for (int c = 0; c < NDC; c++) {
                float4 v = p4[((size_t)c * BB + b0g + bl) * 16 + o4];
                s.x += v.x; s.y += v.y; s.z += v.z; s.w += v.w;
            }
            o4p[(size_t)(b0g + bl) * 16 + o4] = s;
        }
    }
}

// ---------------------------------------------------------------- launch
extern "C" void kernel_launch(void* const* d_in, const int* in_sizes, int n_in,
                              void* d_out, int out_size) {
    const float* x      = (const float*)d_in[0];   // [8192, 64]
    const float* coeffs = (const float*)d_in[1];   // [64, 64, 64]
    const float* bias   = (const float*)d_in[2];   // [64]
    float* out = (float*)d_out;                    // [8192, 64]

    const int smem_main = 2 * SLICE_BYTES + DCH * BT * 4 + 16;   // 82960 (R7 size)
    cudaFuncSetAttribute(kan_main, cudaFuncAttributeMaxDynamicSharedMemorySize, smem_main);

    kan_prep<<<dim3(DD, 9), 256>>>(coeffs);
    kan_main<<<dim3(NBT, NDC), 512, smem_main>>>(x, bias, out);
}

// round 13
// speedup vs baseline: 1.9739x; 1.0022x over previous
#include <cuda_runtime.h>
#include <cuda_fp16.h>
#include <cstdint>

// Problem constants: B=8192, O=64, D=64, K=64
#define BB   8192
#define OO   64
#define DD   64
#define JJN  65                 // 0 = left-linear, 1..63 cubic, 64 = right-linear
#define SLICE (JJN * 32)        // uint4 entries per d-slice = 2080 (fp16-packed, o-pairs)
#define SLICE_BYTES (SLICE * 16) // 33280
#define NDC  4                  // d-chunks (split-K)
#define DCH  (DD / NDC)         // 16
#define BT   256                // b-tile per CTA
#define NBT  (BB / BT)          // 32
#define NTHR 1024               // 32 warps -> 8 warps/SMSP (latency hiding)
#define BPW  8                  // b's per warp

typedef unsigned long long u64;

// Static device scratch
__device__ uint4 g_Ph[DD * SLICE];        // packed cubic coeffs, 2.13 MB
__device__ float g_part[NDC * BB * OO];   // split-K partials, 8 MB

// ---------------------------------------------------------------- asm helpers
__device__ __forceinline__ u64 pk2(float a, float b) {
    u64 r; asm("mov.b64 %0, {%1, %2};" : "=l"(r) : "f"(a), "f"(b)); return r;
}
__device__ __forceinline__ float2 upk2(u64 a) {
    float2 r; asm("mov.b64 {%0, %1}, %2;" : "=f"(r.x), "=f"(r.y) : "l"(a)); return r;
}
__device__ __forceinline__ u64 add2(u64 a, u64 b) {
    u64 d; asm("add.rn.f32x2 %0, %1, %2;" : "=l"(d) : "l"(a), "l"(b)); return d;
}
__device__ __forceinline__ void mbar_init(uint32_t mbar, uint32_t cnt) {
    asm volatile("mbarrier.init.shared.b64 [%0], %1;" :: "r"(mbar), "r"(cnt) : "memory");
}
__device__ __forceinline__ void mbar_expect_tx(uint32_t mbar, uint32_t bytes) {
    asm volatile("mbarrier.arrive.expect_tx.shared::cta.b64 _, [%0], %1;"
                 :: "r"(mbar), "r"(bytes) : "memory");
}
__device__ __forceinline__ void bulk_g2s(uint32_t dst, const void* src, uint32_t bytes,
                                         uint32_t mbar) {
    asm volatile("cp.async.bulk.shared::cta.global.mbarrier::complete_tx::bytes "
                 "[%0], [%1], %2, [%3];"
                 :: "r"(dst), "l"(src), "r"(bytes), "r"(mbar) : "memory");
}
__device__ __forceinline__ void mbar_wait(uint32_t mbar, uint32_t parity) {
    asm volatile(
        "{\n"
        ".reg .pred P;\n"
        "W%=:\n"
        "mbarrier.try_wait.parity.acquire.cta.shared::cta.b64 P, [%0], %1, 0x989680;\n"
        "@P bra D%=;\n"
        "bra W%=;\n"
        "D%=:\n"
        "}"
        :: "r"(mbar), "r"(parity) : "memory");
}

// ---------------------------------------------------------------- PCHIP (exact reference math)
__device__ __forceinline__ float pchip_end(float d0, float d1) {
    float s = 0.5f * (3.0f * d0 - d1);
    if (s * d0 <= 0.0f) s = 0.0f;
    else if (d0 * d1 < 0.0f && fabsf(s) > 3.0f * fabsf(d0)) s = 3.0f * d0;
    return s;
}
__device__ __forceinline__ float pchip_mid(float dp, float dn) {
    return (dp * dn > 0.0f) ? (2.0f * dp * dn / (dp + dn + 1e-12f)) : 0.0f;
}
__device__ __forceinline__ float4 pchip_emit(int jj, float ya, float yb, float yc, float yd) {
    const float inv_h = 15.75f;     // 63/4 exact
    const float h = 4.0f / 63.0f;
    float dab = (yb - ya) * inv_h;
    float dbc = (yc - yb) * inv_h;
    float dcd = (yd - yc) * inv_h;
    float4 p;
    if (jj == 0) {
        p = make_float4(ya, h * pchip_end(dab, dbc), 0.0f, 0.0f);
    } else if (jj == 64) {
        p = make_float4(yd, h * pchip_end(dcd, dbc), 0.0f, 0.0f);
    } else {
        float y0v, y1v, m0v, m1v;
        if (jj == 1)       { y0v = ya; y1v = yb; m0v = pchip_end(dab, dbc); m1v = pchip_mid(dab, dbc); }
        else if (jj == 63) { y0v = yc; y1v = yd; m0v = pchip_mid(dbc, dcd); m1v = pchip_end(dcd, dbc); }
        else               { y0v = yb; y1v = yc; m0v = pchip_mid(dab, dbc); m1v = pchip_mid(dbc, dcd); }
        float M0 = h * m0v, M1 = h * m1v;
        p.x = y0v;
        p.y = M0;
        p.z = -3.0f * y0v + 3.0f * y1v - 2.0f * M0 - M1;
        p.w =  2.0f * y0v - 2.0f * y1v + M0 + M1;
    }
    return p;
}

// ---------------------------------------------------------------- prep (R10 version, measured 5.6us)
// grid (DD, 9), 256 threads. CTA (d, blk) covers jj in [blk*8, blk*8+7] (clip at 64).
__global__ __launch_bounds__(256) void kan_prep(const float* __restrict__ coeffs) {
    __shared__ float sy[OO * 17];   // [o][kk], 16-knot window + pad

    const int d   = blockIdx.x;
    const int blk = blockIdx.y;
    const int lo  = blk * 8;
    const int wa  = min(max((lo - 2) & ~3, 0), 48);   // aligned window [wa, wa+15]

    {
        int o = threadIdx.x >> 2, qd = (threadIdx.x & 3) << 2;
        float4 v = *reinterpret_cast<const float4*>(coeffs + (o << 12) + (d << 6) + wa + qd);
        float* r = sy + o * 17 + qd;
        r[0] = v.x; r[1] = v.y; r[2] = v.z; r[3] = v.w;
    }
    __syncthreads();

    const int wi = threadIdx.x >> 5, lane = threadIdx.x & 31;
    const int jj = lo + wi;
    if (jj > 64) return;

    int s = (jj == 0) ? 0 : ((jj == 64) ? 60 : min(max(jj - 2, 0), 60));
    int base = s - wa;                          // in [0, 12]

    const float* r0 = &sy[lane * 17 + base];
    const float* r1 = &sy[(lane + 32) * 17 + base];
    float4 pa = pchip_emit(jj, r0[0], r0[1], r0[2], r0[3]);
    float4 pb = pchip_emit(jj, r1[0], r1[1], r1[2], r1[3]);

    __half2 h0 = __floats2half2_rn(pa.x, pb.x);
    __half2 h1 = __floats2half2_rn(pa.y, pb.y);
    __half2 h2 = __floats2half2_rn(pa.z, pb.z);
    __half2 h3 = __floats2half2_rn(pa.w, pb.w);
    uint4 q;
    q.x = *reinterpret_cast<uint32_t*>(&h0);
    q.y = *reinterpret_cast<uint32_t*>(&h1);
    q.z = *reinterpret_cast<uint32_t*>(&h2);
    q.w = *reinterpret_cast<uint32_t*>(&h3);
    g_Ph[d * SLICE + (jj << 5) + lane] = q;
}

// ---------------------------------------------------------------- main contraction
// grid (NBT, NDC) = (32, 4) = 128 CTAs, 1024 threads = 32 warps (8/SMSP).
// R7 staging skeleton: depth-2 cp.async.bulk, ph0/ph1, per-dd __syncthreads.
// Warp handles 8 b's; lanes index o-pair (o, o+32) via fp16-packed uint4 rows.
__global__ __launch_bounds__(NTHR, 1) void kan_main(const float* __restrict__ x,
                                                    float* __restrict__ part) {
    extern __shared__ char smraw[];
    uint4* sP = reinterpret_cast<uint4*>(smraw);                      // 2 * SLICE uint4
    float* sx = reinterpret_cast<float*>(smraw + 2 * SLICE_BYTES);    // DCH * BT floats
    uint32_t mbarBase = (uint32_t)__cvta_generic_to_shared(
        smraw + 2 * SLICE_BYTES + DCH * BT * 4);                      // 2 x 8B mbarriers
    uint32_t sb = (uint32_t)__cvta_generic_to_shared(sP);

    const int bt = blockIdx.x, dc = blockIdx.y;
    const int tid = threadIdx.x;
    const int w = tid >> 5, lane = tid & 31;
    const int dbase = dc * DCH;
    const int b0g = bt * BT;

    // load x tile [BT][DCH] -> sx[dd][b_local]  (one float4 per thread)
    {
        int bl = tid >> 2, seg = tid & 3;
        float4 v = *reinterpret_cast<const float4*>(x + (size_t)(b0g + bl) * DD + dbase + seg * 4);
        sx[(seg * 4 + 0) * BT + bl] = v.x;
        sx[(seg * 4 + 1) * BT + bl] = v.y;
        sx[(seg * 4 + 2) * BT + bl] = v.z;
        sx[(seg * 4 + 3) * BT + bl] = v.w;
    }

    if (tid == 0) {
        mbar_init(mbarBase, 1);
        mbar_init(mbarBase + 8, 1);
    }
    __syncthreads();   // mbar init visible + sx done

    auto issue = [&](int dd, int which) {
        uint32_t mb = mbarBase + (uint32_t)which * 8;
        mbar_expect_tx(mb, SLICE_BYTES);
        bulk_g2s(sb + (uint32_t)which * SLICE_BYTES,
                 g_Ph + (size_t)(dbase + dd) * SLICE, SLICE_BYTES, mb);
    };
    if (tid == 0) { issue(0, 0); issue(1, 1); }

    u64 acc[BPW];
    #pragma unroll
    for (int i = 0; i < BPW; i++) acc[i] = 0ULL;   // bit pattern of (0.f, 0.f)

    uint32_t ph0 = 0, ph1 = 0;

    for (int dd = 0; dd < DCH; dd++) {
        int which = dd & 1;
        if (which == 0) { mbar_wait(mbarBase, ph0);     ph0 ^= 1; }
        else            { mbar_wait(mbarBase + 8, ph1); ph1 ^= 1; }
        uint4* cur = sP + which * SLICE;

        // per-lane (jj, u) for this warp's 8 b's (lanes 8-31 mirror 0-7),
        // packed as (off << 16) | fp16(u)
        float xv = sx[dd * BT + (w << 3) + (lane & 7)];
        float t = (xv + 2.0f) * 15.75f;
        float f = fminf(fmaxf(floorf(t), 0.0f), 62.0f);
        int jj; float u;
        if (t < 0.0f)       { jj = 0;  u = t; }
        else if (t > 63.0f) { jj = 64; u = t - 63.0f; }
        else                { jj = (int)f + 1; u = t - f; }
        unsigned pk = ((unsigned)(jj << 5) << 16) |
                      (unsigned)__half_as_ushort(__float2half_rn(u));

        #pragma unroll
        for (int i = 0; i < BPW; i++) {
            unsigned p   = __shfl_sync(0xffffffffu, pk, i);
            unsigned off = p >> 16;
            unsigned u2b = __byte_perm(p, p, 0x1010);     // half2(u, u)
            uint4 q = cur[off + lane];
            __half2 uu = *reinterpret_cast<__half2*>(&u2b);
            __half2 hc0 = *reinterpret_cast<__half2*>(&q.x);
            __half2 hc1 = *reinterpret_cast<__half2*>(&q.y);
            __half2 hc2 = *reinterpret_cast<__half2*>(&q.z);
            __half2 hc3 = *reinterpret_cast<__half2*>(&q.w);
            __half2 r = __hfma2(hc3, uu, hc2);
            r = __hfma2(r, uu, hc1);
            r = __hfma2(r, uu, hc0);
            float2 rf = __half22float2(r);
            acc[i] = add2(acc[i], pk2(rf.x, rf.y));
        }

        __syncthreads();   // all warps done reading buffer `which`
        if (dd + 2 < DCH && tid == 0) issue(dd + 2, which);
    }

    // partials: part[dc][b][o]
    float* pdst = part + ((size_t)dc * BB + b0g + (w << 3)) * OO;
    #pragma unroll
    for (int i = 0; i < BPW; i++) {
        float2 v = upk2(acc[i]);
        pdst[i * OO + lane]      = v.x;
        pdst[i * OO + 32 + lane] = v.y;
    }
}

// ---------------------------------------------------------------- split-K reduce + bias (float4)
__global__ void kan_reduce(const float* __restrict__ part, const float* __restrict__ bias,
                           float* __restrict__ out) {
    int idx = blockIdx.x * 256 + threadIdx.x;     // over B*O/4
    const float4* p4 = reinterpret_cast<const float4*>(part);
    float4 s = reinterpret_cast<const float4*>(bias)[idx & 15];
    #pragma unroll
    for (int c = 0; c < NDC; c++) {
        float4 v = p4[(size_t)c * (BB * OO / 4) + idx];
        s.x += v.x; s.y += v.y; s.z += v.z; s.w += v.w;
    }
    reinterpret_cast<float4*>(out)[idx] = s;
}

// ---------------------------------------------------------------- launch
extern "C" void kernel_launch(void* const* d_in, const int* in_sizes, int n_in,
                              void* d_out, int out_size) {
    const float* x      = (const float*)d_in[0];   // [8192, 64]
    const float* coeffs = (const float*)d_in[1];   // [64, 64, 64]
    const float* bias   = (const float*)d_in[2];   // [64]
    float* out = (float*)d_out;                    // [8192, 64]

    float* prt; cudaGetSymbolAddress((void**)&prt, g_part);

    const int smem_main = 2 * SLICE_BYTES + DCH * BT * 4 + 16;   // 82960
    cudaFuncSetAttribute(kan_main, cudaFuncAttributeMaxDynamicSharedMemorySize, smem_main);

    kan_prep<<<dim3(DD, 9), 256>>>(coeffs);
    kan_main<<<dim3(NBT, NDC), NTHR, smem_main>>>(x, prt);
    kan_reduce<<<(BB * OO / 4) / 256, 256>>>(prt, bias, out);
}

// round 14
// speedup vs baseline: 2.1216x; 1.0749x over previous
#include <cuda_runtime.h>
#include <cuda_fp16.h>
#include <cstdint>

// Problem constants: B=8192, O=64, D=64, K=64
#define BB   8192
#define OO   64
#define DD   64
#define JJN  65                 // 0 = left-linear, 1..63 cubic, 64 = right-linear
#define SLICE (JJN * 32)        // uint4 entries per d-slice = 2080 (fp16-packed, o-pairs)
#define SLICE_BYTES (SLICE * 16) // 33280
#define NDC  4                  // d-chunks (split-K)
#define DCH  (DD / NDC)         // 16
#define BT   256                // b-tile per CTA
#define NBT  (BB / BT)          // 32

typedef unsigned long long u64;

// Static device scratch
__device__ uint4 g_Ph[DD * SLICE];        // packed cubic coeffs, 2.13 MB
__device__ float g_part[NDC * BB * OO];   // split-K partials, 8 MB

// ---------------------------------------------------------------- asm helpers
__device__ __forceinline__ u64 pk2(float a, float b) {
    u64 r; asm("mov.b64 %0, {%1, %2};" : "=l"(r) : "f"(a), "f"(b)); return r;
}
__device__ __forceinline__ float2 upk2(u64 a) {
    float2 r; asm("mov.b64 {%0, %1}, %2;" : "=f"(r.x), "=f"(r.y) : "l"(a)); return r;
}
__device__ __forceinline__ u64 add2(u64 a, u64 b) {
    u64 d; asm("add.rn.f32x2 %0, %1, %2;" : "=l"(d) : "l"(a), "l"(b)); return d;
}
__device__ __forceinline__ void mbar_init(uint32_t mbar, uint32_t cnt) {
    asm volatile("mbarrier.init.shared.b64 [%0], %1;" :: "r"(mbar), "r"(cnt) : "memory");
}
__device__ __forceinline__ void mbar_expect_tx(uint32_t mbar, uint32_t bytes) {
    asm volatile("mbarrier.arrive.expect_tx.shared::cta.b64 _, [%0], %1;"
                 :: "r"(mbar), "r"(bytes) : "memory");
}
__device__ __forceinline__ void bulk_g2s(uint32_t dst, const void* src, uint32_t bytes,
                                         uint32_t mbar) {
    asm volatile("cp.async.bulk.shared::cta.global.mbarrier::complete_tx::bytes "
                 "[%0], [%1], %2, [%3];"
                 :: "r"(dst), "l"(src), "r"(bytes), "r"(mbar) : "memory");
}
__device__ __forceinline__ void mbar_wait(uint32_t mbar, uint32_t parity) {
    asm volatile(
        "{\n"
        ".reg .pred P;\n"
        "W%=:\n"
        "mbarrier.try_wait.parity.acquire.cta.shared::cta.b64 P, [%0], %1, 0x989680;\n"
        "@P bra D%=;\n"
        "bra W%=;\n"
        "D%=:\n"
        "}"
        :: "r"(mbar), "r"(parity) : "memory");
}

// ---------------------------------------------------------------- PCHIP (exact reference math)
__device__ __forceinline__ float pchip_end(float d0, float d1) {
    float s = 0.5f * (3.0f * d0 - d1);
    if (s * d0 <= 0.0f) s = 0.0f;
    else if (d0 * d1 < 0.0f && fabsf(s) > 3.0f * fabsf(d0)) s = 3.0f * d0;
    return s;
}
__device__ __forceinline__ float pchip_mid(float dp, float dn) {
    return (dp * dn > 0.0f) ? (2.0f * dp * dn / (dp + dn + 1e-12f)) : 0.0f;
}
__device__ __forceinline__ float4 pchip_emit(int jj, float ya, float yb, float yc, float yd) {
    const float inv_h = 15.75f;     // 63/4 exact
    const float h = 4.0f / 63.0f;
    float dab = (yb - ya) * inv_h;
    float dbc = (yc - yb) * inv_h;
    float dcd = (yd - yc) * inv_h;
    float4 p;
    if (jj == 0) {
        p = make_float4(ya, h * pchip_end(dab, dbc), 0.0f, 0.0f);
    } else if (jj == 64) {
        p = make_float4(yd, h * pchip_end(dcd, dbc), 0.0f, 0.0f);
    } else {
        float y0v, y1v, m0v, m1v;
        if (jj == 1)       { y0v = ya; y1v = yb; m0v = pchip_end(dab, dbc); m1v = pchip_mid(dab, dbc); }
        else if (jj == 63) { y0v = yc; y1v = yd; m0v = pchip_mid(dbc, dcd); m1v = pchip_end(dcd, dbc); }
        else               { y0v = yb; y1v = yc; m0v = pchip_mid(dab, dbc); m1v = pchip_mid(dbc, dcd); }
        float M0 = h * m0v, M1 = h * m1v;
        p.x = y0v;
        p.y = M0;
        p.z = -3.0f * y0v + 3.0f * y1v - 2.0f * M0 - M1;
        p.w =  2.0f * y0v - 2.0f * y1v + M0 + M1;
    }
    return p;
}

// ---------------------------------------------------------------- prep (R10 body + early PDL trigger)
// grid (DD, 9), 256 threads. CTA (d, blk) covers jj in [blk*8, blk*8+7] (clip at 64).
__global__ __launch_bounds__(256) void kan_prep(const float* __restrict__ coeffs) {
    // release the dependent kan_main launch immediately; it gridsyncs before touching g_Ph
    cudaTriggerProgrammaticLaunchCompletion();

    __shared__ float sy[OO * 17];   // [o][kk], 16-knot window + pad

    const int d   = blockIdx.x;
    const int blk = blockIdx.y;
    const int lo  = blk * 8;
    const int wa  = min(max((lo - 2) & ~3, 0), 48);   // aligned window [wa, wa+15]

    {
        int o = threadIdx.x >> 2, qd = (threadIdx.x & 3) << 2;
        float4 v = *reinterpret_cast<const float4*>(coeffs + (o << 12) + (d << 6) + wa + qd);
        float* r = sy + o * 17 + qd;
        r[0] = v.x; r[1] = v.y; r[2] = v.z; r[3] = v.w;
    }
    __syncthreads();

    const int wi = threadIdx.x >> 5, lane = threadIdx.x & 31;
    const int jj = lo + wi;
    if (jj > 64) return;

    int s = (jj == 0) ? 0 : ((jj == 64) ? 60 : min(max(jj - 2, 0), 60));
    int base = s - wa;                          // in [0, 12]

    const float* r0 = &sy[lane * 17 + base];
    const float* r1 = &sy[(lane + 32) * 17 + base];
    float4 pa = pchip_emit(jj, r0[0], r0[1], r0[2], r0[3]);
    float4 pb = pchip_emit(jj, r1[0], r1[1], r1[2], r1[3]);

    __half2 h0 = __floats2half2_rn(pa.x, pb.x);
    __half2 h1 = __floats2half2_rn(pa.y, pb.y);
    __half2 h2 = __floats2half2_rn(pa.z, pb.z);
    __half2 h3 = __floats2half2_rn(pa.w, pb.w);
    uint4 q;
    q.x = *reinterpret_cast<uint32_t*>(&h0);
    q.y = *reinterpret_cast<uint32_t*>(&h1);
    q.z = *reinterpret_cast<uint32_t*>(&h2);
    q.w = *reinterpret_cast<uint32_t*>(&h3);
    g_Ph[d * SLICE + (jj << 5) + lane] = q;
}

// ---------------------------------------------------------------- main contraction (R7 skeleton + PDL)
// grid (NBT, NDC) = (32, 4) = 128 CTAs, 512 threads = 16 warps.
// Prelude (x load, mbar init) overlaps prep via PDL; gridsync gates the first DMA.
__global__ __launch_bounds__(512, 1) void kan_main(const float* __restrict__ x,
                                                   float* __restrict__ part) {
    extern __shared__ char smraw[];
    uint4* sP = reinterpret_cast<uint4*>(smraw);                      // 2 * SLICE uint4
    float* sx = reinterpret_cast<float*>(smraw + 2 * SLICE_BYTES);    // DCH * BT floats
    uint32_t mbarBase = (uint32_t)__cvta_generic_to_shared(
        smraw + 2 * SLICE_BYTES + DCH * BT * 4);                      // 2 x 8B mbarriers
    uint32_t sb = (uint32_t)__cvta_generic_to_shared(sP);

    const int bt = blockIdx.x, dc = blockIdx.y;
    const int tid = threadIdx.x;
    const int w = tid >> 5, lane = tid & 31;
    const int dbase = dc * DCH;
    const int b0g = bt * BT;

    // load x tile [BT][DCH] -> sx[dd][b_local]   (overlaps prep's tail via PDL)
    for (int e = tid; e < BT * 4; e += 512) {
        int bl = e >> 2, seg = e & 3;
        float4 v = *reinterpret_cast<const float4*>(x + (size_t)(b0g + bl) * DD + dbase + seg * 4);
        sx[(seg * 4 + 0) * BT + bl] = v.x;
        sx[(seg * 4 + 1) * BT + bl] = v.y;
        sx[(seg * 4 + 2) * BT + bl] = v.z;
        sx[(seg * 4 + 3) * BT + bl] = v.w;
    }

    if (tid == 0) {
        mbar_init(mbarBase, 1);
        mbar_init(mbarBase + 8, 1);
    }
    __syncthreads();   // mbar init visible + sx done

    auto issue = [&](int dd, int which) {
        uint32_t mb = mbarBase + (uint32_t)which * 8;
        mbar_expect_tx(mb, SLICE_BYTES);
        bulk_g2s(sb + (uint32_t)which * SLICE_BYTES,
                 g_Ph + (size_t)(dbase + dd) * SLICE, SLICE_BYTES, mb);
    };
    if (tid == 0) {
        cudaGridDependencySynchronize();   // wait for kan_prep grid before reading g_Ph
        issue(0, 0); issue(1, 1);
    }

    u64 acc[16];
    #pragma unroll
    for (int i = 0; i < 16; i++) acc[i] = 0ULL;   // bit pattern of (0.f, 0.f)

    uint32_t ph0 = 0, ph1 = 0;
    const char* curBase0 = smraw + (size_t)lane * 16;

    for (int dd = 0; dd < DCH; dd++) {
        int which = dd & 1;
        if (which == 0) { mbar_wait(mbarBase, ph0);     ph0 ^= 1; }
        else            { mbar_wait(mbarBase + 8, ph1); ph1 ^= 1; }
        const char* cur = curBase0 + (size_t)which * SLICE_BYTES;

        // per-lane (jj, u) for this warp's 16 b's (lanes 16-31 mirror 0-15),
        // packed as (byte_off << 16) | fp16(u), byte_off = jj*512 (fits 16 bits)
        float xv = sx[dd * BT + (w << 4) + (lane & 15)];
        float t = (xv + 2.0f) * 15.75f;
        float f = fminf(fmaxf(floorf(t), 0.0f), 62.0f);
        int jj; float u;
        if (t < 0.0f)       { jj = 0;  u = t; }
        else if (t > 63.0f) { jj = 64; u = t - 63.0f; }
        else                { jj = (int)f + 1; u = t - f; }
        unsigned pk = ((unsigned)(jj << 9) << 16) |
                      (unsigned)__half_as_ushort(__float2half_rn(u));

        #pragma unroll
        for (int i = 0; i < 16; i++) {
            unsigned p   = __shfl_sync(0xffffffffu, pk, i);
            unsigned off = p >> 16;                       // byte offset of row
            unsigned u2b = __byte_perm(p, p, 0x1010);     // half2(u, u)
            uint4 q = *reinterpret_cast<const uint4*>(cur + off);
            __half2 uu = *reinterpret_cast<__half2*>(&u2b);
            __half2 hc0 = *reinterpret_cast<__half2*>(&q.x);
            __half2 hc1 = *reinterpret_cast<__half2*>(&q.y);
            __half2 hc2 = *reinterpret_cast<__half2*>(&q.z);
            __half2 hc3 = *reinterpret_cast<__half2*>(&q.w);
            __half2 r = __hfma2(hc3, uu, hc2);
            r = __hfma2(r, uu, hc1);
            r = __hfma2(r, uu, hc0);
            float2 rf = __half22float2(r);
            acc[i] = add2(acc[i], pk2(rf.x, rf.y));
        }

        __syncthreads();   // all warps done reading buffer `which`
        if (dd + 2 < DCH && tid == 0) issue(dd + 2, which);
    }

    // partials: part[dc][b][o]
    float* pdst = part + ((size_t)dc * BB + b0g + (w << 4)) * OO;
    #pragma unroll
    for (int i = 0; i < 16; i++) {
        float2 v = upk2(acc[i]);
        pdst[i * OO + lane]      = v.x;
        pdst[i * OO + 32 + lane] = v.y;
    }
}

// ---------------------------------------------------------------- split-K reduce + bias (float4, PDL)
__global__ void kan_reduce(const float* __restrict__ part, const float* __restrict__ bias,
                           float* __restrict__ out) {
    cudaGridDependencySynchronize();   // wait for kan_main grid before reading partials
    int idx = blockIdx.x * 256 + threadIdx.x;     // over B*O/4
    const float4* p4 = reinterpret_cast<const float4*>(part);
    float4 s = reinterpret_cast<const float4*>(bias)[idx & 15];
    #pragma unroll
    for (int c = 0; c < NDC; c++) {
        float4 v = p4[(size_t)c * (BB * OO / 4) + idx];
        s.x += v.x; s.y += v.y; s.z += v.z; s.w += v.w;
    }
    reinterpret_cast<float4*>(out)[idx] = s;
}

// ---------------------------------------------------------------- launch
extern "C" void kernel_launch(void* const* d_in, const int* in_sizes, int n_in,
                              void* d_out, int out_size) {
    const float* x      = (const float*)d_in[0];   // [8192, 64]
    const float* coeffs = (const float*)d_in[1];   // [64, 64, 64]
    const float* bias   = (const float*)d_in[2];   // [64]
    float* out = (float*)d_out;                    // [8192, 64]

    float* prt; cudaGetSymbolAddress((void**)&prt, g_part);

    const int smem_main = 2 * SLICE_BYTES + DCH * BT * 4 + 16;   // 82960
    cudaFuncSetAttribute(kan_main, cudaFuncAttributeMaxDynamicSharedMemorySize, smem_main);

    // kernel 1: normal launch
    kan_prep<<<dim3(DD, 9), 256>>>(coeffs);

    // kernel 2: PDL launch (overlaps prep; gridsync gates g_Ph reads)
    cudaLaunchAttribute attr[1];
    attr[0].id = cudaLaunchAttributeProgrammaticStreamSerialization;
    attr[0].val.programmaticStreamSerializationAllowed = 1;

    cudaLaunchConfig_t cfg = {};
    cfg.gridDim = dim3(NBT, NDC, 1);
    cfg.blockDim = dim3(512, 1, 1);
    cfg.dynamicSmemBytes = smem_main;
    cfg.stream = 0;
    cfg.attrs = attr;
    cfg.numAttrs = 1;
    cudaLaunchKernelEx(&cfg, kan_main, x, prt);

    // kernel 3: PDL launch (hides launch latency; gridsync gates partials reads)
    cudaLaunchConfig_t cfg2 = {};
    cfg2.gridDim = dim3((BB * OO / 4) / 256, 1, 1);
    cfg2.blockDim = dim3(256, 1, 1);
    cfg2.dynamicSmemBytes = 0;
    cfg2.stream = 0;
    cfg2.attrs = attr;
    cfg2.numAttrs = 1;
    cudaLaunchKernelEx(&cfg2, kan_reduce, (const float*)prt, bias, out);
}

// round 15
// speedup vs baseline: 2.5229x; 1.1892x over previous
#include <cuda_runtime.h>
#include <cuda_fp16.h>
#include <cstdint>

// Problem constants: B=8192, O=64, D=64, K=64
#define BB   8192
#define OO   64
#define DD   64
#define JJN  65                 // 0 = left-linear, 1..63 cubic, 64 = right-linear
#define SLICE (JJN * 32)        // uint4 entries per d-slice = 2080 (fp16-packed, o-pairs)
#define SLICE_BYTES (SLICE * 16) // 33280
#define PAIRB (2 * SLICE_BYTES)  // 66560 bytes: two consecutive d-slices per DMA
#define NDC  4                  // d-chunks (split-K)
#define DCH  (DD / NDC)         // 16
#define NPAIR (DCH / 2)         // 8 pair-iterations
#define BT   256                // b-tile per CTA
#define NBT  (BB / BT)          // 32

typedef unsigned long long u64;

// Static device scratch
__device__ uint4 g_Ph[DD * SLICE];        // packed cubic coeffs, 2.13 MB
__device__ float g_part[NDC * BB * OO];   // split-K partials, 8 MB

// ---------------------------------------------------------------- asm helpers
__device__ __forceinline__ u64 pk2(float a, float b) {
    u64 r; asm("mov.b64 %0, {%1, %2};" : "=l"(r) : "f"(a), "f"(b)); return r;
}
__device__ __forceinline__ float2 upk2(u64 a) {
    float2 r; asm("mov.b64 {%0, %1}, %2;" : "=f"(r.x), "=f"(r.y) : "l"(a)); return r;
}
__device__ __forceinline__ u64 add2(u64 a, u64 b) {
    u64 d; asm("add.rn.f32x2 %0, %1, %2;" : "=l"(d) : "l"(a), "l"(b)); return d;
}
__device__ __forceinline__ void mbar_init(uint32_t mbar, uint32_t cnt) {
    asm volatile("mbarrier.init.shared.b64 [%0], %1;" :: "r"(mbar), "r"(cnt) : "memory");
}
__device__ __forceinline__ void mbar_expect_tx(uint32_t mbar, uint32_t bytes) {
    asm volatile("mbarrier.arrive.expect_tx.shared::cta.b64 _, [%0], %1;"
                 :: "r"(mbar), "r"(bytes) : "memory");
}
__device__ __forceinline__ void bulk_g2s(uint32_t dst, const void* src, uint32_t bytes,
                                         uint32_t mbar) {
    asm volatile("cp.async.bulk.shared::cta.global.mbarrier::complete_tx::bytes "
                 "[%0], [%1], %2, [%3];"
                 :: "r"(dst), "l"(src), "r"(bytes), "r"(mbar) : "memory");
}
__device__ __forceinline__ void mbar_wait(uint32_t mbar, uint32_t parity) {
    asm volatile(
        "{\n"
        ".reg .pred P;\n"
        "W%=:\n"
        "mbarrier.try_wait.parity.acquire.cta.shared::cta.b64 P, [%0], %1, 0x989680;\n"
        "@P bra D%=;\n"
        "bra W%=;\n"
        "D%=:\n"
        "}"
        :: "r"(mbar), "r"(parity) : "memory");
}

// ---------------------------------------------------------------- PCHIP (exact reference math)
__device__ __forceinline__ float pchip_end(float d0, float d1) {
    float s = 0.5f * (3.0f * d0 - d1);
    if (s * d0 <= 0.0f) s = 0.0f;
    else if (d0 * d1 < 0.0f && fabsf(s) > 3.0f * fabsf(d0)) s = 3.0f * d0;
    return s;
}
__device__ __forceinline__ float pchip_mid(float dp, float dn) {
    return (dp * dn > 0.0f) ? (2.0f * dp * dn / (dp + dn + 1e-12f)) : 0.0f;
}
__device__ __forceinline__ float4 pchip_emit(int jj, float ya, float yb, float yc, float yd) {
    const float inv_h = 15.75f;     // 63/4 exact
    const float h = 4.0f / 63.0f;
    float dab = (yb - ya) * inv_h;
    float dbc = (yc - yb) * inv_h;
    float dcd = (yd - yc) * inv_h;
    float4 p;
    if (jj == 0) {
        p = make_float4(ya, h * pchip_end(dab, dbc), 0.0f, 0.0f);
    } else if (jj == 64) {
        p = make_float4(yd, h * pchip_end(dcd, dbc), 0.0f, 0.0f);
    } else {
        float y0v, y1v, m0v, m1v;
        if (jj == 1)       { y0v = ya; y1v = yb; m0v = pchip_end(dab, dbc); m1v = pchip_mid(dab, dbc); }
        else if (jj == 63) { y0v = yc; y1v = yd; m0v = pchip_mid(dbc, dcd); m1v = pchip_end(dcd, dbc); }
        else               { y0v = yb; y1v = yc; m0v = pchip_mid(dab, dbc); m1v = pchip_mid(dbc, dcd); }
        float M0 = h * m0v, M1 = h * m1v;
        p.x = y0v;
        p.y = M0;
        p.z = -3.0f * y0v + 3.0f * y1v - 2.0f * M0 - M1;
        p.w =  2.0f * y0v - 2.0f * y1v + M0 + M1;
    }
    return p;
}

// ---------------------------------------------------------------- prep (R10 body + early PDL trigger)
__global__ __launch_bounds__(256) void kan_prep(const float* __restrict__ coeffs) {
    cudaTriggerProgrammaticLaunchCompletion();

    __shared__ float sy[OO * 17];   // [o][kk], 16-knot window + pad

    const int d   = blockIdx.x;
    const int blk = blockIdx.y;
    const int lo  = blk * 8;
    const int wa  = min(max((lo - 2) & ~3, 0), 48);   // aligned window [wa, wa+15]

    {
        int o = threadIdx.x >> 2, qd = (threadIdx.x & 3) << 2;
        float4 v = *reinterpret_cast<const float4*>(coeffs + (o << 12) + (d << 6) + wa + qd);
        float* r = sy + o * 17 + qd;
        r[0] = v.x; r[1] = v.y; r[2] = v.z; r[3] = v.w;
    }
    __syncthreads();

    const int wi = threadIdx.x >> 5, lane = threadIdx.x & 31;
    const int jj = lo + wi;
    if (jj > 64) return;

    int s = (jj == 0) ? 0 : ((jj == 64) ? 60 : min(max(jj - 2, 0), 60));
    int base = s - wa;                          // in [0, 12]

    const float* r0 = &sy[lane * 17 + base];
    const float* r1 = &sy[(lane + 32) * 17 + base];
    float4 pa = pchip_emit(jj, r0[0], r0[1], r0[2], r0[3]);
    float4 pb = pchip_emit(jj, r1[0], r1[1], r1[2], r1[3]);

    __half2 h0 = __floats2half2_rn(pa.x, pb.x);
    __half2 h1 = __floats2half2_rn(pa.y, pb.y);
    __half2 h2 = __floats2half2_rn(pa.z, pb.z);
    __half2 h3 = __floats2half2_rn(pa.w, pb.w);
    uint4 q;
    q.x = *reinterpret_cast<uint32_t*>(&h0);
    q.y = *reinterpret_cast<uint32_t*>(&h1);
    q.z = *reinterpret_cast<uint32_t*>(&h2);
    q.w = *reinterpret_cast<uint32_t*>(&h3);
    g_Ph[d * SLICE + (jj << 5) + lane] = q;
}

// ---------------------------------------------------------------- main contraction
// grid (NBT, NDC) = (32, 4) = 128 CTAs, 512 threads = 16 warps.
// PAIRED staging: one 66.5 KB cp.async.bulk covers 2 consecutive d-slices;
// 8 pair-iterations -> half the barriers/mbar_waits, 4-slice lookahead.
__global__ __launch_bounds__(512, 1) void kan_main(const float* __restrict__ x,
                                                   float* __restrict__ part) {
    extern __shared__ char smraw[];
    float* sx = reinterpret_cast<float*>(smraw + 2 * PAIRB);          // DCH * BT floats
    uint32_t mbarBase = (uint32_t)__cvta_generic_to_shared(
        smraw + 2 * PAIRB + DCH * BT * 4);                            // 2 x 8B mbarriers
    uint32_t sb = (uint32_t)__cvta_generic_to_shared(smraw);

    const int bt = blockIdx.x, dc = blockIdx.y;
    const int tid = threadIdx.x;
    const int w = tid >> 5, lane = tid & 31;
    const int dbase = dc * DCH;
    const int b0g = bt * BT;

    // load x tile [BT][DCH] -> sx[dd][b_local]   (overlaps prep's tail via PDL)
    for (int e = tid; e < BT * 4; e += 512) {
        int bl = e >> 2, seg = e & 3;
        float4 v = *reinterpret_cast<const float4*>(x + (size_t)(b0g + bl) * DD + dbase + seg * 4);
        sx[(seg * 4 + 0) * BT + bl] = v.x;
        sx[(seg * 4 + 1) * BT + bl] = v.y;
        sx[(seg * 4 + 2) * BT + bl] = v.z;
        sx[(seg * 4 + 3) * BT + bl] = v.w;
    }

    if (tid == 0) {
        mbar_init(mbarBase, 1);
        mbar_init(mbarBase + 8, 1);
    }
    __syncthreads();   // mbar init visible + sx done

    auto issue = [&](int pair, int which) {
        uint32_t mb = mbarBase + (uint32_t)which * 8;
        mbar_expect_tx(mb, PAIRB);
        bulk_g2s(sb + (uint32_t)which * PAIRB,
                 g_Ph + (size_t)(dbase + 2 * pair) * SLICE, PAIRB, mb);
    };
    if (tid == 0) {
        cudaGridDependencySynchronize();   // wait for kan_prep grid before reading g_Ph
        issue(0, 0); issue(1, 1);
    }

    u64 acc[16];
    #pragma unroll
    for (int i = 0; i < 16; i++) acc[i] = 0ULL;   // bit pattern of (0.f, 0.f)

    const char* laneBase = smraw + (size_t)lane * 16;

    for (int p = 0; p < NPAIR; p++) {
        int which = p & 1;
        mbar_wait(mbarBase + which * 8, (uint32_t)(p >> 1) & 1);

        #pragma unroll
        for (int sub = 0; sub < 2; sub++) {
            const int dd = 2 * p + sub;
            const char* cur = laneBase + (size_t)which * PAIRB + (size_t)sub * SLICE_BYTES;

            // per-lane (jj, u) for this warp's 16 b's (lanes 16-31 mirror 0-15),
            // packed as (byte_off << 16) | fp16(u), byte_off = jj*512 (fits 16 bits)
            float xv = sx[dd * BT + (w << 4) + (lane & 15)];
            float t = (xv + 2.0f) * 15.75f;
            float f = fminf(fmaxf(floorf(t), 0.0f), 62.0f);
            int jj; float u;
            if (t < 0.0f)       { jj = 0;  u = t; }
            else if (t > 63.0f) { jj = 64; u = t - 63.0f; }
            else                { jj = (int)f + 1; u = t - f; }
            unsigned pk = ((unsigned)(jj << 9) << 16) |
                          (unsigned)__half_as_ushort(__float2half_rn(u));

            #pragma unroll
            for (int i = 0; i < 16; i++) {
                unsigned pv  = __shfl_sync(0xffffffffu, pk, i);
                unsigned off = pv >> 16;                       // byte offset of row
                unsigned u2b = __byte_perm(pv, pv, 0x1010);    // half2(u, u)
                uint4 q = *reinterpret_cast<const uint4*>(cur + off);
                __half2 uu = *reinterpret_cast<__half2*>(&u2b);
                __half2 hc0 = *reinterpret_cast<__half2*>(&q.x);
                __half2 hc1 = *reinterpret_cast<__half2*>(&q.y);
                __half2 hc2 = *reinterpret_cast<__half2*>(&q.z);
                __half2 hc3 = *reinterpret_cast<__half2*>(&q.w);
                __half2 r = __hfma2(hc3, uu, hc2);
                r = __hfma2(r, uu, hc1);
                r = __hfma2(r, uu, hc0);
                float2 rf = __half22float2(r);
                acc[i] = add2(acc[i], pk2(rf.x, rf.y));
            }
        }

        __syncthreads();   // all warps done reading buffer `which`
        if (p + 2 < NPAIR && tid == 0) issue(p + 2, which);
    }

    // partials: part[dc][b][o]
    float* pdst = part + ((size_t)dc * BB + b0g + (w << 4)) * OO;
    #pragma unroll
    for (int i = 0; i < 16; i++) {
        float2 v = upk2(acc[i]);
        pdst[i * OO + lane]      = v.x;
        pdst[i * OO + 32 + lane] = v.y;
    }
}

// ---------------------------------------------------------------- split-K reduce + bias (float4, PDL)
__global__ void kan_reduce(const float* __restrict__ part, const float* __restrict__ bias,
                           float* __restrict__ out) {
    cudaGridDependencySynchronize();   // wait for kan_main grid before reading partials
    int idx = blockIdx.x * 256 + threadIdx.x;     // over B*O/4
    const float4* p4 = reinterpret_cast<const float4*>(part);
    float4 s = reinterpret_cast<const float4*>(bias)[idx & 15];
    #pragma unroll
    for (int c = 0; c < NDC; c++) {
        float4 v = p4[(size_t)c * (BB * OO / 4) + idx];
        s.x += v.x; s.y += v.y; s.z += v.z; s.w += v.w;
    }
    reinterpret_cast<float4*>(out)[idx] = s;
}

// ---------------------------------------------------------------- launch
extern "C" void kernel_launch(void* const* d_in, const int* in_sizes, int n_in,
                              void* d_out, int out_size) {
    const float* x      = (const float*)d_in[0];   // [8192, 64]
    const float* coeffs = (const float*)d_in[1];   // [64, 64, 64]
    const float* bias   = (const float*)d_in[2];   // [64]
    float* out = (float*)d_out;                    // [8192, 64]

    float* prt; cudaGetSymbolAddress((void**)&prt, g_part);

    const int smem_main = 2 * PAIRB + DCH * BT * 4 + 16;   // 133120 + 16384 + 16 = 149520
    cudaFuncSetAttribute(kan_main, cudaFuncAttributeMaxDynamicSharedMemorySize, smem_main);

    // kernel 1: normal launch
    kan_prep<<<dim3(DD, 9), 256>>>(coeffs);

    // kernel 2: PDL launch (overlaps prep; gridsync gates g_Ph reads)
    cudaLaunchAttribute attr[1];
    attr[0].id = cudaLaunchAttributeProgrammaticStreamSerialization;
    attr[0].val.programmaticStreamSerializationAllowed = 1;

    cudaLaunchConfig_t cfg = {};
    cfg.gridDim = dim3(NBT, NDC, 1);
    cfg.blockDim = dim3(512, 1, 1);
    cfg.dynamicSmemBytes = smem_main;
    cfg.stream = 0;
    cfg.attrs = attr;
    cfg.numAttrs = 1;
    cudaLaunchKernelEx(&cfg, kan_main, x, prt);

    // kernel 3: PDL launch (hides launch latency; gridsync gates partials reads)
    cudaLaunchConfig_t cfg2 = {};
    cfg2.gridDim = dim3((BB * OO / 4) / 256, 1, 1);
    cfg2.blockDim = dim3(256, 1, 1);
    cfg2.dynamicSmemBytes = 0;
    cfg2.stream = 0;
    cfg2.attrs = attr;
    cfg2.numAttrs = 1;
    cudaLaunchKernelEx(&cfg2, kan_reduce, (const float*)prt, bias, out);
}

// round 16
// speedup vs baseline: 2.5549x; 1.0127x over previous
#include <cuda_runtime.h>
#include <cuda_fp16.h>
#include <cstdint>

// Problem constants: B=8192, O=64, D=64, K=64
#define BB   8192
#define OO   64
#define DD   64
#define JJN  65                 // 0 = left-linear, 1..63 cubic, 64 = right-linear
#define SLICE (JJN * 32)        // uint4 entries per d-slice = 2080 (fp16-packed, o-pairs)
#define SLICE_BYTES (SLICE * 16) // 33280
#define PAIRB (2 * SLICE_BYTES)  // 66560 bytes: two consecutive d-slices per DMA
#define NDC  4                  // d-chunks (split-K)
#define DCH  (DD / NDC)         // 16
#define NPAIR (DCH / 2)         // 8 pair-iterations
#define BT   256                // b-tile per CTA
#define NBT  (BB / BT)          // 32

typedef unsigned long long u64;

// Static device scratch
__device__ uint4 g_Ph[DD * SLICE];        // packed cubic coeffs, 2.13 MB
__device__ float g_part[NDC * BB * OO];   // split-K partials, 8 MB

// ---------------------------------------------------------------- asm helpers
__device__ __forceinline__ u64 pk2(float a, float b) {
    u64 r; asm("mov.b64 %0, {%1, %2};" : "=l"(r) : "f"(a), "f"(b)); return r;
}
__device__ __forceinline__ float2 upk2(u64 a) {
    float2 r; asm("mov.b64 {%0, %1}, %2;" : "=f"(r.x), "=f"(r.y) : "l"(a)); return r;
}
__device__ __forceinline__ u64 add2(u64 a, u64 b) {
    u64 d; asm("add.rn.f32x2 %0, %1, %2;" : "=l"(d) : "l"(a), "l"(b)); return d;
}
__device__ __forceinline__ void mbar_init(uint32_t mbar, uint32_t cnt) {
    asm volatile("mbarrier.init.shared.b64 [%0], %1;" :: "r"(mbar), "r"(cnt) : "memory");
}
__device__ __forceinline__ void mbar_expect_tx(uint32_t mbar, uint32_t bytes) {
    asm volatile("mbarrier.arrive.expect_tx.shared::cta.b64 _, [%0], %1;"
                 :: "r"(mbar), "r"(bytes) : "memory");
}
__device__ __forceinline__ void bulk_g2s(uint32_t dst, const void* src, uint32_t bytes,
                                         uint32_t mbar) {
    asm volatile("cp.async.bulk.shared::cta.global.mbarrier::complete_tx::bytes "
                 "[%0], [%1], %2, [%3];"
                 :: "r"(dst), "l"(src), "r"(bytes), "r"(mbar) : "memory");
}
__device__ __forceinline__ void mbar_wait(uint32_t mbar, uint32_t parity) {
    asm volatile(
        "{\n"
        ".reg .pred P;\n"
        "W%=:\n"
        "mbarrier.try_wait.parity.acquire.cta.shared::cta.b64 P, [%0], %1, 0x989680;\n"
        "@P bra D%=;\n"
        "bra W%=;\n"
        "D%=:\n"
        "}"
        :: "r"(mbar), "r"(parity) : "memory");
}
__device__ __forceinline__ void bar_arrive(int id) {
    asm volatile("bar.arrive %0, 512;" :: "r"(id) : "memory");
}
__device__ __forceinline__ void bar_wait(int id) {
    asm volatile("bar.sync %0, 512;" :: "r"(id) : "memory");
}

// ---------------------------------------------------------------- PCHIP (exact reference math)
__device__ __forceinline__ float pchip_end(float d0, float d1) {
    float s = 0.5f * (3.0f * d0 - d1);
    if (s * d0 <= 0.0f) s = 0.0f;
    else if (d0 * d1 < 0.0f && fabsf(s) > 3.0f * fabsf(d0)) s = 3.0f * d0;
    return s;
}
__device__ __forceinline__ float pchip_mid(float dp, float dn) {
    return (dp * dn > 0.0f) ? (2.0f * dp * dn / (dp + dn + 1e-12f)) : 0.0f;
}
__device__ __forceinline__ float4 pchip_emit(int jj, float ya, float yb, float yc, float yd) {
    const float inv_h = 15.75f;     // 63/4 exact
    const float h = 4.0f / 63.0f;
    float dab = (yb - ya) * inv_h;
    float dbc = (yc - yb) * inv_h;
    float dcd = (yd - yc) * inv_h;
    float4 p;
    if (jj == 0) {
        p = make_float4(ya, h * pchip_end(dab, dbc), 0.0f, 0.0f);
    } else if (jj == 64) {
        p = make_float4(yd, h * pchip_end(dcd, dbc), 0.0f, 0.0f);
    } else {
        float y0v, y1v, m0v, m1v;
        if (jj == 1)       { y0v = ya; y1v = yb; m0v = pchip_end(dab, dbc); m1v = pchip_mid(dab, dbc); }
        else if (jj == 63) { y0v = yc; y1v = yd; m0v = pchip_mid(dbc, dcd); m1v = pchip_end(dcd, dbc); }
        else               { y0v = yb; y1v = yc; m0v = pchip_mid(dab, dbc); m1v = pchip_mid(dbc, dcd); }
        float M0 = h * m0v, M1 = h * m1v;
        p.x = y0v;
        p.y = M0;
        p.z = -3.0f * y0v + 3.0f * y1v - 2.0f * M0 - M1;
        p.w =  2.0f * y0v - 2.0f * y1v + M0 + M1;
    }
    return p;
}

// ---------------------------------------------------------------- prep (R10 body + early PDL trigger)
__global__ __launch_bounds__(256) void kan_prep(const float* __restrict__ coeffs) {
    cudaTriggerProgrammaticLaunchCompletion();

    __shared__ float sy[OO * 17];   // [o][kk], 16-knot window + pad

    const int d   = blockIdx.x;
    const int blk = blockIdx.y;
    const int lo  = blk * 8;
    const int wa  = min(max((lo - 2) & ~3, 0), 48);   // aligned window [wa, wa+15]

    {
        int o = threadIdx.x >> 2, qd = (threadIdx.x & 3) << 2;
        float4 v = *reinterpret_cast<const float4*>(coeffs + (o << 12) + (d << 6) + wa + qd);
        float* r = sy + o * 17 + qd;
        r[0] = v.x; r[1] = v.y; r[2] = v.z; r[3] = v.w;
    }
    __syncthreads();

    const int wi = threadIdx.x >> 5, lane = threadIdx.x & 31;
    const int jj = lo + wi;
    if (jj > 64) return;

    int s = (jj == 0) ? 0 : ((jj == 64) ? 60 : min(max(jj - 2, 0), 60));
    int base = s - wa;                          // in [0, 12]

    const float* r0 = &sy[lane * 17 + base];
    const float* r1 = &sy[(lane + 32) * 17 + base];
    float4 pa = pchip_emit(jj, r0[0], r0[1], r0[2], r0[3]);
    float4 pb = pchip_emit(jj, r1[0], r1[1], r1[2], r1[3]);

    __half2 h0 = __floats2half2_rn(pa.x, pb.x);
    __half2 h1 = __floats2half2_rn(pa.y, pb.y);
    __half2 h2 = __floats2half2_rn(pa.z, pb.z);
    __half2 h3 = __floats2half2_rn(pa.w, pb.w);
    uint4 q;
    q.x = *reinterpret_cast<uint32_t*>(&h0);
    q.y = *reinterpret_cast<uint32_t*>(&h1);
    q.z = *reinterpret_cast<uint32_t*>(&h2);
    q.w = *reinterpret_cast<uint32_t*>(&h3);
    g_Ph[d * SLICE + (jj << 5) + lane] = q;
}

// ---------------------------------------------------------------- main contraction
// grid (NBT, NDC) = (32, 4) = 128 CTAs, 512 threads = 16 warps.
// PAIRED staging (R15) + producer-only-waits: consumers bar.arrive and keep
// flowing; only warp 0 bar.syncs (absorbs skew) before refilling the buffer.
// Two alternating named barrier IDs prevent the double-arrival race (a fast
// warp blocks on the un-refilled mbar before it could arrive twice on one ID).
__global__ __launch_bounds__(512, 1) void kan_main(const float* __restrict__ x,
                                                   float* __restrict__ part) {
    extern __shared__ char smraw[];
    float* sx = reinterpret_cast<float*>(smraw + 2 * PAIRB);          // DCH * BT floats
    uint32_t mbarBase = (uint32_t)__cvta_generic_to_shared(
        smraw + 2 * PAIRB + DCH * BT * 4);                            // 2 x 8B mbarriers
    uint32_t sb = (uint32_t)__cvta_generic_to_shared(smraw);

    const int bt = blockIdx.x, dc = blockIdx.y;
    const int tid = threadIdx.x;
    const int w = tid >> 5, lane = tid & 31;
    const int dbase = dc * DCH;
    const int b0g = bt * BT;

    // load x tile [BT][DCH] -> sx[dd][b_local]   (overlaps prep's tail via PDL)
    for (int e = tid; e < BT * 4; e += 512) {
        int bl = e >> 2, seg = e & 3;
        float4 v = *reinterpret_cast<const float4*>(x + (size_t)(b0g + bl) * DD + dbase + seg * 4);
        sx[(seg * 4 + 0) * BT + bl] = v.x;
        sx[(seg * 4 + 1) * BT + bl] = v.y;
        sx[(seg * 4 + 2) * BT + bl] = v.z;
        sx[(seg * 4 + 3) * BT + bl] = v.w;
    }

    if (tid == 0) {
        mbar_init(mbarBase, 1);
        mbar_init(mbarBase + 8, 1);
    }
    __syncthreads();   // mbar init visible + sx done

    auto issue = [&](int pair, int which) {
        uint32_t mb = mbarBase + (uint32_t)which * 8;
        mbar_expect_tx(mb, PAIRB);
        bulk_g2s(sb + (uint32_t)which * PAIRB,
                 g_Ph + (size_t)(dbase + 2 * pair) * SLICE, PAIRB, mb);
    };
    if (tid == 0) {
        cudaGridDependencySynchronize();   // wait for kan_prep grid before reading g_Ph
        issue(0, 0); issue(1, 1);
    }

    u64 acc[16];
    #pragma unroll
    for (int i = 0; i < 16; i++) acc[i] = 0ULL;   // bit pattern of (0.f, 0.f)

    const char* laneBase = smraw + (size_t)lane * 16;

    for (int p = 0; p < NPAIR; p++) {
        int which = p & 1;
        mbar_wait(mbarBase + which * 8, (uint32_t)(p >> 1) & 1);

        #pragma unroll
        for (int sub = 0; sub < 2; sub++) {
            const int dd = 2 * p + sub;
            const char* cur = laneBase + (size_t)which * PAIRB + (size_t)sub * SLICE_BYTES;

            // per-lane (jj, u) for this warp's 16 b's (lanes 16-31 mirror 0-15),
            // packed as (byte_off << 16) | fp16(u), byte_off = jj*512 (fits 16 bits)
            float xv = sx[dd * BT + (w << 4) + (lane & 15)];
            float t = (xv + 2.0f) * 15.75f;
            float f = fminf(fmaxf(floorf(t), 0.0f), 62.0f);
            int jj; float u;
            if (t < 0.0f)       { jj = 0;  u = t; }
            else if (t > 63.0f) { jj = 64; u = t - 63.0f; }
            else                { jj = (int)f + 1; u = t - f; }
            unsigned pk = ((unsigned)(jj << 9) << 16) |
                          (unsigned)__half_as_ushort(__float2half_rn(u));

            #pragma unroll
            for (int i = 0; i < 16; i++) {
                unsigned pv  = __shfl_sync(0xffffffffu, pk, i);
                unsigned off = pv >> 16;                       // byte offset of row
                unsigned u2b = __byte_perm(pv, pv, 0x1010);    // half2(u, u)
                uint4 q = *reinterpret_cast<const uint4*>(cur + off);
                __half2 uu = *reinterpret_cast<__half2*>(&u2b);
                __half2 hc0 = *reinterpret_cast<__half2*>(&q.x);
                __half2 hc1 = *reinterpret_cast<__half2*>(&q.y);
                __half2 hc2 = *reinterpret_cast<__half2*>(&q.z);
                __half2 hc3 = *reinterpret_cast<__half2*>(&q.w);
                __half2 r = __hfma2(hc3, uu, hc2);
                r = __hfma2(r, uu, hc1);
                r = __hfma2(r, uu, hc0);
                float2 rf = __half22float2(r);
                acc[i] = add2(acc[i], pk2(rf.x, rf.y));
            }
        }

        // producer-only-waits drain protocol (skip when no refill is needed)
        if (p + 2 < NPAIR) {
            int barid = 1 + (p & 1);
            if (w == 0) {
                bar_wait(barid);               // absorb skew in warp 0 only
                if (lane == 0) issue(p + 2, which);
            } else {
                bar_arrive(barid);             // non-blocking release
            }
        }
    }

    // partials: part[dc][b][o]
    float* pdst = part + ((size_t)dc * BB + b0g + (w << 4)) * OO;
    #pragma unroll
    for (int i = 0; i < 16; i++) {
        float2 v = upk2(acc[i]);
        pdst[i * OO + lane]      = v.x;
        pdst[i * OO + 32 + lane] = v.y;
    }
}

// ---------------------------------------------------------------- split-K reduce + bias (float4, PDL)
__global__ void kan_reduce(const float* __restrict__ part, const float* __restrict__ bias,
                           float* __restrict__ out) {
    cudaGridDependencySynchronize();   // wait for kan_main grid before reading partials
    int idx = blockIdx.x * 256 + threadIdx.x;     // over B*O/4
    const float4* p4 = reinterpret_cast<const float4*>(part);
    float4 s = reinterpret_cast<const float4*>(bias)[idx & 15];
    #pragma unroll
    for (int c = 0; c < NDC; c++) {
        float4 v = p4[(size_t)c * (BB * OO / 4) + idx];
        s.x += v.x; s.y += v.y; s.z += v.z; s.w += v.w;
    }
    reinterpret_cast<float4*>(out)[idx] = s;
}

// ---------------------------------------------------------------- launch
extern "C" void kernel_launch(void* const* d_in, const int* in_sizes, int n_in,
                              void* d_out, int out_size) {
    const float* x      = (const float*)d_in[0];   // [8192, 64]
    const float* coeffs = (const float*)d_in[1];   // [64, 64, 64]
    const float* bias   = (const float*)d_in[2];   // [64]
    float* out = (float*)d_out;                    // [8192, 64]

    float* prt; cudaGetSymbolAddress((void**)&prt, g_part);

    const int smem_main = 2 * PAIRB + DCH * BT * 4 + 16;   // 149520
    cudaFuncSetAttribute(kan_main, cudaFuncAttributeMaxDynamicSharedMemorySize, smem_main);

    // kernel 1: normal launch
    kan_prep<<<dim3(DD, 9), 256>>>(coeffs);

    // kernel 2: PDL launch (overlaps prep; gridsync gates g_Ph reads)
    cudaLaunchAttribute attr[1];
    attr[0].id = cudaLaunchAttributeProgrammaticStreamSerialization;
    attr[0].val.programmaticStreamSerializationAllowed = 1;

    cudaLaunchConfig_t cfg = {};
    cfg.gridDim = dim3(NBT, NDC, 1);
    cfg.blockDim = dim3(512, 1, 1);
    cfg.dynamicSmemBytes = smem_main;
    cfg.stream = 0;
    cfg.attrs = attr;
    cfg.numAttrs = 1;
    cudaLaunchKernelEx(&cfg, kan_main, x, prt);

    // kernel 3: PDL launch (hides launch latency; gridsync gates partials reads)
    cudaLaunchConfig_t cfg2 = {};
    cfg2.gridDim = dim3((BB * OO / 4) / 256, 1, 1);
    cfg2.blockDim = dim3(256, 1, 1);
    cfg2.dynamicSmemBytes = 0;
    cfg2.stream = 0;
    cfg2.attrs = attr;
    cfg2.numAttrs = 1;
    cudaLaunchKernelEx(&cfg2, kan_reduce, (const float*)prt, bias, out);
}